// round 2
// baseline (speedup 1.0000x reference)
#include <cuda_runtime.h>

#define B_ 2
#define T_ 2048
#define D_ 512
#define H_ 1024
#define V_ 32000
#define BT_ (B_*T_)
#define NCHUNK 32
#define CHLEN (T_/NCHUNK)   /* 64 */

// ---------------- scratch (static device globals; no allocs allowed) ----------
__device__ float g_emb[BT_ * D_];          // 8 MB   token embeddings
__device__ float g_yh[BT_ * H_];           // 16 MB  emb@Wh (pre-scan), later reused as merged2
__device__ float g_merged[BT_ * 2 * H_];   // 32 MB  [cur_enc | hist_enc]
__device__ float g_normed[BT_ * H_];       // 16 MB  layernorm output
__device__ float g_csum[B_ * NCHUNK * H_]; // 256 KB chunk partial sums

// ---------------- embedding gather -------------------------------------------
__global__ void k_embed(const int* __restrict__ tokens, const float* __restrict__ E) {
    int i = blockIdx.x * blockDim.x + threadIdx.x;      // over BT_*D_/4 float4s
    int row = i / (D_ / 4);
    int c4  = i % (D_ / 4);
    int tok = tokens[row];
    ((float4*)g_emb)[i] = ((const float4*)(E + (size_t)tok * D_))[c4];
}

// ---------------- generic fp32 SGEMM: C[M,N] = epi(A[M,K] @ B[K,N]) ----------
// BM=BN=128, BK=16, 256 threads, 8x8 register tile. All dims divide evenly.
#define BM 128
#define BN 128
#define BKg 16

__global__ __launch_bounds__(256) void sgemm(
    const float* __restrict__ A, const float* __restrict__ Bg,
    float* __restrict__ C,
    int K, int lda, int ldb, int ldc,
    const float* __restrict__ bias, int doRelu, float scale)
{
    __shared__ float As[BKg][BM + 4];
    __shared__ float Bs[BKg][BN + 4];

    int tid = threadIdx.x;
    int tx = tid & 15;        // 0..15 -> column micro-tile
    int ty = tid >> 4;        // 0..15 -> row micro-tile

    const float* Ab = A + (size_t)blockIdx.y * BM * lda;
    const float* Bb = Bg + blockIdx.x * BN;

    float acc[8][8];
    #pragma unroll
    for (int i = 0; i < 8; i++)
        #pragma unroll
        for (int j = 0; j < 8; j++) acc[i][j] = 0.f;

    for (int k0 = 0; k0 < K; k0 += BKg) {
        // A tile: 128x16 -> As[k][m] (transposed store)
        #pragma unroll
        for (int i = 0; i < 2; i++) {
            int f = tid + i * 256;           // 0..511 float4 ids
            int r = f >> 2;                  // row in tile (0..127)
            int c = (f & 3) << 2;            // k-col (0,4,8,12)
            float4 v = *(const float4*)(Ab + (size_t)r * lda + k0 + c);
            As[c + 0][r] = v.x; As[c + 1][r] = v.y;
            As[c + 2][r] = v.z; As[c + 3][r] = v.w;
        }
        // B tile: 16x128 -> Bs[k][n]
        #pragma unroll
        for (int i = 0; i < 2; i++) {
            int f = tid + i * 256;
            int r = f >> 5;                  // k row (0..15)
            int c = (f & 31) << 2;           // n col (0..124 step 4)
            *(float4*)(&Bs[r][c]) = *(const float4*)(Bb + (size_t)(k0 + r) * ldb + c);
        }
        __syncthreads();

        #pragma unroll
        for (int k = 0; k < BKg; k++) {
            float a[8], b[8];
            *(float4*)(a)     = *(const float4*)(&As[k][ty * 8]);
            *(float4*)(a + 4) = *(const float4*)(&As[k][ty * 8 + 4]);
            *(float4*)(b)     = *(const float4*)(&Bs[k][tx * 8]);
            *(float4*)(b + 4) = *(const float4*)(&Bs[k][tx * 8 + 4]);
            #pragma unroll
            for (int i = 0; i < 8; i++)
                #pragma unroll
                for (int j = 0; j < 8; j++)
                    acc[i][j] = fmaf(a[i], b[j], acc[i][j]);
        }
        __syncthreads();
    }

    int row0 = blockIdx.y * BM + ty * 8;
    int col0 = blockIdx.x * BN + tx * 8;
    #pragma unroll
    for (int i = 0; i < 8; i++) {
        #pragma unroll
        for (int j = 0; j < 8; j++) {
            float v = acc[i][j];
            if (bias) v += bias[col0 + j];
            if (doRelu) v = fmaxf(v, 0.f);
            C[(size_t)(row0 + i) * ldc + col0 + j] = v * scale;
        }
    }
}

// ---------------- chunked prefix scan of Yh over t ---------------------------
// Phase 1: per-(b,chunk,h) partial sums
__global__ void k_chunksum() {
    int g = blockIdx.x * blockDim.x + threadIdx.x;      // 65536 threads
    int h = g % H_;
    int c = (g / H_) % NCHUNK;
    int b = g / (H_ * NCHUNK);
    const float* base = g_yh + ((size_t)(b * T_ + c * CHLEN)) * H_ + h;
    float s = 0.f;
    #pragma unroll 8
    for (int j = 0; j < CHLEN; j++) s += base[(size_t)j * H_];
    g_csum[(b * NCHUNK + c) * H_ + h] = s;
}

// Phase 2: exclusive scan of the 32 chunk sums per (b,h)
__global__ void k_scan() {
    int g = blockIdx.x * blockDim.x + threadIdx.x;      // 2048 threads
    int h = g % H_;
    int b = g / H_;
    float run = 0.f;
    #pragma unroll
    for (int c = 0; c < NCHUNK; c++) {
        int idx = (b * NCHUNK + c) * H_ + h;
        float t = g_csum[idx];
        g_csum[idx] = run;
        run += t;
    }
}

// Phase 3: local cumsum + divide-by-count + bias + relu -> hist half of g_merged
__global__ void k_hist(const float* __restrict__ bh) {
    int g = blockIdx.x * blockDim.x + threadIdx.x;      // 65536 threads
    int h = g % H_;
    int c = (g / H_) % NCHUNK;
    int b = g / (H_ * NCHUNK);
    float excl = g_csum[(b * NCHUNK + c) * H_ + h];     // sum of all t' < c*CHLEN
    float bias = bh[h];
    #pragma unroll 4
    for (int j = 0; j < CHLEN; j++) {
        int t = c * CHLEN + j;
        float y = g_yh[((size_t)(b * T_ + t)) * H_ + h];
        float val = (t == 0) ? y : excl / (float)t;     // S[t-1]/t  (t==0: emb[0]@Wh)
        excl += y;
        float o = fmaxf(val + bias, 0.f);
        g_merged[((size_t)(b * T_ + t)) * (2 * H_) + H_ + h] = o;
    }
}

// ---------------- LayerNorm over H=1024 per row -------------------------------
__global__ __launch_bounds__(256) void k_ln(const float* __restrict__ X,
                                            const float* __restrict__ w,
                                            const float* __restrict__ b,
                                            float* __restrict__ Y)
{
    int row = blockIdx.x;
    int tid = threadIdx.x;                 // 256 threads * 4 elems = 1024
    const float* x = X + (size_t)row * H_;
    float4 v = ((const float4*)x)[tid];
    float s  = v.x + v.y + v.z + v.w;
    float sq = v.x * v.x + v.y * v.y + v.z * v.z + v.w * v.w;

    __shared__ float sh[2][8];
    #pragma unroll
    for (int o = 16; o; o >>= 1) {
        s  += __shfl_xor_sync(0xffffffffu, s, o);
        sq += __shfl_xor_sync(0xffffffffu, sq, o);
    }
    if ((tid & 31) == 0) { sh[0][tid >> 5] = s; sh[1][tid >> 5] = sq; }
    __syncthreads();
    if (tid < 32) {
        s  = (tid < 8) ? sh[0][tid] : 0.f;
        sq = (tid < 8) ? sh[1][tid] : 0.f;
        #pragma unroll
        for (int o = 4; o; o >>= 1) {
            s  += __shfl_xor_sync(0xffffffffu, s, o);
            sq += __shfl_xor_sync(0xffffffffu, sq, o);
        }
        if (tid == 0) { sh[0][0] = s; sh[1][0] = sq; }
    }
    __syncthreads();
    float mu   = sh[0][0] * (1.f / H_);
    float var  = sh[1][0] * (1.f / H_) - mu * mu;
    float rstd = rsqrtf(var + 1e-5f);

    float4 wv = ((const float4*)w)[tid];
    float4 bv = ((const float4*)b)[tid];
    float4 o;
    o.x = (v.x - mu) * rstd * wv.x + bv.x;
    o.y = (v.y - mu) * rstd * wv.y + bv.y;
    o.z = (v.z - mu) * rstd * wv.z + bv.z;
    o.w = (v.w - mu) * rstd * wv.w + bv.w;
    ((float4*)(Y + (size_t)row * H_))[tid] = o;
}

// ---------------- launch ------------------------------------------------------
extern "C" void kernel_launch(void* const* d_in, const int* in_sizes, int n_in,
                              void* d_out, int out_size)
{
    const int*   tokens = (const int*)  d_in[0];
    const float* E    = (const float*)d_in[1];
    const float* Wc   = (const float*)d_in[2];
    const float* bc   = (const float*)d_in[3];
    const float* Wh   = (const float*)d_in[4];
    const float* bh   = (const float*)d_in[5];
    const float* Wm   = (const float*)d_in[6];
    const float* bm   = (const float*)d_in[7];
    const float* Wo   = (const float*)d_in[8];
    const float* bo   = (const float*)d_in[9];
    const float* ln_w = (const float*)d_in[10];
    const float* ln_b = (const float*)d_in[11];
    float* out = (float*)d_out;

    float *emb, *yh, *merged, *normed;
    cudaGetSymbolAddress((void**)&emb,    g_emb);
    cudaGetSymbolAddress((void**)&yh,     g_yh);
    cudaGetSymbolAddress((void**)&merged, g_merged);
    cudaGetSymbolAddress((void**)&normed, g_normed);

    // 1) gather embeddings
    k_embed<<<(BT_ * D_ / 4) / 256, 256>>>(tokens, E);

    // 2) cur_enc = relu(emb@Wc + bc)  -> left half of g_merged (ldc = 2H)
    sgemm<<<dim3(H_ / BN, BT_ / BM), 256>>>(emb, Wc, merged,
                                            D_, D_, H_, 2 * H_, bc, 1, 1.f);

    // 3) Yh = emb@Wh (no epilogue)
    sgemm<<<dim3(H_ / BN, BT_ / BM), 256>>>(emb, Wh, yh,
                                            D_, D_, H_, H_, nullptr, 0, 1.f);

    // 4-6) hist_enc = relu(cumsum(Yh)/count + bh) -> right half of g_merged
    k_chunksum<<<(B_ * NCHUNK * H_) / 256, 256>>>();
    k_scan<<<(B_ * H_) / 256, 256>>>();
    k_hist<<<(B_ * NCHUNK * H_) / 256, 256>>>(bh);

    // 7) merged2 = relu(merged@Wm + bm)  (K=2048) -> reuse g_yh
    sgemm<<<dim3(H_ / BN, BT_ / BM), 256>>>(merged, Wm, yh,
                                            2 * H_, 2 * H_, H_, H_, bm, 1, 1.f);

    // 8) layernorm
    k_ln<<<BT_, 256>>>(yh, ln_w, ln_b, normed);

    // 9) logits = (normed@Wo + bo) * 0.1   (the big one: 268 GF)
    sgemm<<<dim3(V_ / BN, BT_ / BM), 256>>>(normed, Wo, out,
                                            H_, H_, V_, V_, bo, 0, 0.1f);
}

// round 3
// speedup vs baseline: 1.0006x; 1.0006x over previous
#include <cuda_runtime.h>

#define B_ 2
#define T_ 2048
#define D_ 512
#define H_ 1024
#define V_ 32000
#define BT_ (B_*T_)
#define NCHUNK 32
#define CHLEN (T_/NCHUNK)   /* 64 */

// ---------------- scratch (static device globals; no allocs allowed) ----------
__device__ float g_emb[BT_ * D_];          // 8 MB   token embeddings
__device__ float g_yh[BT_ * H_];           // 16 MB  emb@Wh (pre-scan), later reused as merged2
__device__ float g_merged[BT_ * 2 * H_];   // 32 MB  [cur_enc | hist_enc]
__device__ float g_normed[BT_ * H_];       // 16 MB  layernorm output
__device__ float g_csum[B_ * NCHUNK * H_]; // 256 KB chunk partial sums

// ---------------- embedding gather -------------------------------------------
__global__ void k_embed(const int* __restrict__ tokens, const float* __restrict__ E) {
    int i = blockIdx.x * blockDim.x + threadIdx.x;      // over BT_*D_/4 float4s
    int row = i / (D_ / 4);
    int c4  = i % (D_ / 4);
    int tok = tokens[row];
    ((float4*)g_emb)[i] = ((const float4*)(E + (size_t)tok * D_))[c4];
}

// ---------------- generic fp32 SGEMM: C[M,N] = epi(A[M,K] @ B[K,N]) ----------
// BM=BN=128, BK=16, 256 threads, 8x8 register tile. All dims divide evenly.
#define BM 128
#define BN 128
#define BKg 16

__global__ __launch_bounds__(256) void sgemm(
    const float* __restrict__ A, const float* __restrict__ Bg,
    float* __restrict__ C,
    int K, int lda, int ldb, int ldc,
    const float* __restrict__ bias, int doRelu, float scale)
{
    __shared__ float As[BKg][BM + 4];
    __shared__ float Bs[BKg][BN + 4];

    int tid = threadIdx.x;
    int tx = tid & 15;        // 0..15 -> column micro-tile
    int ty = tid >> 4;        // 0..15 -> row micro-tile

    const float* Ab = A + (size_t)blockIdx.y * BM * lda;
    const float* Bb = Bg + blockIdx.x * BN;

    float acc[8][8];
    #pragma unroll
    for (int i = 0; i < 8; i++)
        #pragma unroll
        for (int j = 0; j < 8; j++) acc[i][j] = 0.f;

    for (int k0 = 0; k0 < K; k0 += BKg) {
        // A tile: 128x16 -> As[k][m] (transposed store)
        #pragma unroll
        for (int i = 0; i < 2; i++) {
            int f = tid + i * 256;           // 0..511 float4 ids
            int r = f >> 2;                  // row in tile (0..127)
            int c = (f & 3) << 2;            // k-col (0,4,8,12)
            float4 v = *(const float4*)(Ab + (size_t)r * lda + k0 + c);
            As[c + 0][r] = v.x; As[c + 1][r] = v.y;
            As[c + 2][r] = v.z; As[c + 3][r] = v.w;
        }
        // B tile: 16x128 -> Bs[k][n]
        #pragma unroll
        for (int i = 0; i < 2; i++) {
            int f = tid + i * 256;
            int r = f >> 5;                  // k row (0..15)
            int c = (f & 31) << 2;           // n col (0..124 step 4)
            *(float4*)(&Bs[r][c]) = *(const float4*)(Bb + (size_t)(k0 + r) * ldb + c);
        }
        __syncthreads();

        #pragma unroll
        for (int k = 0; k < BKg; k++) {
            float a[8], b[8];
            *(float4*)(a)     = *(const float4*)(&As[k][ty * 8]);
            *(float4*)(a + 4) = *(const float4*)(&As[k][ty * 8 + 4]);
            *(float4*)(b)     = *(const float4*)(&Bs[k][tx * 8]);
            *(float4*)(b + 4) = *(const float4*)(&Bs[k][tx * 8 + 4]);
            #pragma unroll
            for (int i = 0; i < 8; i++)
                #pragma unroll
                for (int j = 0; j < 8; j++)
                    acc[i][j] = fmaf(a[i], b[j], acc[i][j]);
        }
        __syncthreads();
    }

    int row0 = blockIdx.y * BM + ty * 8;
    int col0 = blockIdx.x * BN + tx * 8;
    #pragma unroll
    for (int i = 0; i < 8; i++) {
        #pragma unroll
        for (int j = 0; j < 8; j++) {
            float v = acc[i][j];
            if (bias) v += bias[col0 + j];
            if (doRelu) v = fmaxf(v, 0.f);
            C[(size_t)(row0 + i) * ldc + col0 + j] = v * scale;
        }
    }
}

// ---------------- chunked prefix scan of Yh over t ---------------------------
// Phase 1: per-(b,chunk,h) partial sums
__global__ void k_chunksum() {
    int g = blockIdx.x * blockDim.x + threadIdx.x;      // 65536 threads
    int h = g % H_;
    int c = (g / H_) % NCHUNK;
    int b = g / (H_ * NCHUNK);
    const float* base = g_yh + ((size_t)(b * T_ + c * CHLEN)) * H_ + h;
    float s = 0.f;
    #pragma unroll 8
    for (int j = 0; j < CHLEN; j++) s += base[(size_t)j * H_];
    g_csum[(b * NCHUNK + c) * H_ + h] = s;
}

// Phase 2: exclusive scan of the 32 chunk sums per (b,h)
__global__ void k_scan() {
    int g = blockIdx.x * blockDim.x + threadIdx.x;      // 2048 threads
    int h = g % H_;
    int b = g / H_;
    float run = 0.f;
    #pragma unroll
    for (int c = 0; c < NCHUNK; c++) {
        int idx = (b * NCHUNK + c) * H_ + h;
        float t = g_csum[idx];
        g_csum[idx] = run;
        run += t;
    }
}

// Phase 3: local cumsum + divide-by-count + bias + relu -> hist half of g_merged
__global__ void k_hist(const float* __restrict__ bh) {
    int g = blockIdx.x * blockDim.x + threadIdx.x;      // 65536 threads
    int h = g % H_;
    int c = (g / H_) % NCHUNK;
    int b = g / (H_ * NCHUNK);
    float excl = g_csum[(b * NCHUNK + c) * H_ + h];     // sum of all t' < c*CHLEN
    float bias = bh[h];
    #pragma unroll 4
    for (int j = 0; j < CHLEN; j++) {
        int t = c * CHLEN + j;
        float y = g_yh[((size_t)(b * T_ + t)) * H_ + h];
        float val = (t == 0) ? y : excl / (float)t;     // S[t-1]/t  (t==0: emb[0]@Wh)
        excl += y;
        float o = fmaxf(val + bias, 0.f);
        g_merged[((size_t)(b * T_ + t)) * (2 * H_) + H_ + h] = o;
    }
}

// ---------------- LayerNorm over H=1024 per row -------------------------------
__global__ __launch_bounds__(256) void k_ln(const float* __restrict__ X,
                                            const float* __restrict__ w,
                                            const float* __restrict__ b,
                                            float* __restrict__ Y)
{
    int row = blockIdx.x;
    int tid = threadIdx.x;                 // 256 threads * 4 elems = 1024
    const float* x = X + (size_t)row * H_;
    float4 v = ((const float4*)x)[tid];
    float s  = v.x + v.y + v.z + v.w;
    float sq = v.x * v.x + v.y * v.y + v.z * v.z + v.w * v.w;

    __shared__ float sh[2][8];
    #pragma unroll
    for (int o = 16; o; o >>= 1) {
        s  += __shfl_xor_sync(0xffffffffu, s, o);
        sq += __shfl_xor_sync(0xffffffffu, sq, o);
    }
    if ((tid & 31) == 0) { sh[0][tid >> 5] = s; sh[1][tid >> 5] = sq; }
    __syncthreads();
    if (tid < 32) {
        s  = (tid < 8) ? sh[0][tid] : 0.f;
        sq = (tid < 8) ? sh[1][tid] : 0.f;
        #pragma unroll
        for (int o = 4; o; o >>= 1) {
            s  += __shfl_xor_sync(0xffffffffu, s, o);
            sq += __shfl_xor_sync(0xffffffffu, sq, o);
        }
        if (tid == 0) { sh[0][0] = s; sh[1][0] = sq; }
    }
    __syncthreads();
    float mu   = sh[0][0] * (1.f / H_);
    float var  = sh[1][0] * (1.f / H_) - mu * mu;
    float rstd = rsqrtf(var + 1e-5f);

    float4 wv = ((const float4*)w)[tid];
    float4 bv = ((const float4*)b)[tid];
    float4 o;
    o.x = (v.x - mu) * rstd * wv.x + bv.x;
    o.y = (v.y - mu) * rstd * wv.y + bv.y;
    o.z = (v.z - mu) * rstd * wv.z + bv.z;
    o.w = (v.w - mu) * rstd * wv.w + bv.w;
    ((float4*)(Y + (size_t)row * H_))[tid] = o;
}

// ---------------- launch ------------------------------------------------------
extern "C" void kernel_launch(void* const* d_in, const int* in_sizes, int n_in,
                              void* d_out, int out_size)
{
    const int*   tokens = (const int*)  d_in[0];
    const float* E    = (const float*)d_in[1];
    const float* Wc   = (const float*)d_in[2];
    const float* bc   = (const float*)d_in[3];
    const float* Wh   = (const float*)d_in[4];
    const float* bh   = (const float*)d_in[5];
    const float* Wm   = (const float*)d_in[6];
    const float* bm   = (const float*)d_in[7];
    const float* Wo   = (const float*)d_in[8];
    const float* bo   = (const float*)d_in[9];
    const float* ln_w = (const float*)d_in[10];
    const float* ln_b = (const float*)d_in[11];
    float* out = (float*)d_out;

    float *emb, *yh, *merged, *normed;
    cudaGetSymbolAddress((void**)&emb,    g_emb);
    cudaGetSymbolAddress((void**)&yh,     g_yh);
    cudaGetSymbolAddress((void**)&merged, g_merged);
    cudaGetSymbolAddress((void**)&normed, g_normed);

    // 1) gather embeddings
    k_embed<<<(BT_ * D_ / 4) / 256, 256>>>(tokens, E);

    // 2) cur_enc = relu(emb@Wc + bc)  -> left half of g_merged (ldc = 2H)
    sgemm<<<dim3(H_ / BN, BT_ / BM), 256>>>(emb, Wc, merged,
                                            D_, D_, H_, 2 * H_, bc, 1, 1.f);

    // 3) Yh = emb@Wh (no epilogue)
    sgemm<<<dim3(H_ / BN, BT_ / BM), 256>>>(emb, Wh, yh,
                                            D_, D_, H_, H_, nullptr, 0, 1.f);

    // 4-6) hist_enc = relu(cumsum(Yh)/count + bh) -> right half of g_merged
    k_chunksum<<<(B_ * NCHUNK * H_) / 256, 256>>>();
    k_scan<<<(B_ * H_) / 256, 256>>>();
    k_hist<<<(B_ * NCHUNK * H_) / 256, 256>>>(bh);

    // 7) merged2 = relu(merged@Wm + bm)  (K=2048) -> reuse g_yh
    sgemm<<<dim3(H_ / BN, BT_ / BM), 256>>>(merged, Wm, yh,
                                            2 * H_, 2 * H_, H_, H_, bm, 1, 1.f);

    // 8) layernorm
    k_ln<<<BT_, 256>>>(yh, ln_w, ln_b, normed);

    // 9) logits = (normed@Wo + bo) * 0.1   (the big one: 268 GF)
    sgemm<<<dim3(V_ / BN, BT_ / BM), 256>>>(normed, Wo, out,
                                            H_, H_, V_, V_, bo, 0, 0.1f);
}

// round 4
// speedup vs baseline: 3.2408x; 3.2387x over previous
#include <cuda_runtime.h>
#include <cstdint>

#define B_ 2
#define T_ 2048
#define D_ 512
#define H_ 1024
#define V_ 32000
#define BT_ (B_*T_)
#define NCHUNK 32
#define CHLEN (T_/NCHUNK)   /* 64 */

// ---------------- scratch (static device globals; no allocs allowed) ----------
__device__ float g_emb[BT_ * D_];          // 8 MB   token embeddings
__device__ float g_yh[BT_ * H_];           // 16 MB  emb@Wh (pre-scan), later merged2
__device__ float g_merged[BT_ * 2 * H_];   // 32 MB  [cur_enc | hist_enc]
__device__ float g_normed[BT_ * H_];       // 16 MB  layernorm output
__device__ float g_csum[B_ * NCHUNK * H_]; // 256 KB chunk partial sums

// ---------------- embedding gather -------------------------------------------
__global__ void k_embed(const int* __restrict__ tokens, const float* __restrict__ E) {
    int i = blockIdx.x * blockDim.x + threadIdx.x;      // over BT_*D_/4 float4s
    int row = i / (D_ / 4);
    int c4  = i % (D_ / 4);
    int tok = tokens[row];
    ((float4*)g_emb)[i] = ((const float4*)(E + (size_t)tok * D_))[c4];
}

// =================== tf32 tensor-core GEMM =====================================
// C[M,N] = epi(A[M,K] @ B[K,N]); BM=BN=128, BK=32, 256 thr (8 warps, 2x4),
// warp tile 64x32, mma.sync.m16n8k8.tf32, cp.async double buffer.
#define BM 128
#define BN 128
#define BK 32
#define ASTRIDE 36      /* words; bank = (4m+k)%32 -> conflict-free frag loads */
#define BSTRIDE 136     /* words; bank = (8k+n)%32 -> conflict-free frag loads */
#define A_STAGE (BM*ASTRIDE)        /* 4608 */
#define B_STAGE (BK*BSTRIDE)        /* 4352 */
#define SMEM_BYTES ((2*A_STAGE + 2*B_STAGE) * 4)   /* 71680 */

__device__ __forceinline__ uint32_t f2tf32(float x) {
    uint32_t r;
    asm("cvt.rna.tf32.f32 %0, %1;" : "=r"(r) : "f"(x));
    return r;
}

__device__ __forceinline__ void cpasync16(float* s, const float* g) {
    uint32_t sa = (uint32_t)__cvta_generic_to_shared(s);
    asm volatile("cp.async.cg.shared.global [%0], [%1], 16;\n" :: "r"(sa), "l"(g));
}

__global__ __launch_bounds__(256) void tf32gemm(
    const float* __restrict__ A, const float* __restrict__ Bg,
    float* __restrict__ C,
    int K, int lda, int ldb, int ldc,
    const float* __restrict__ bias, int doRelu, float scale)
{
    extern __shared__ float sh[];
    float* As = sh;                    // 2 stages of [BM][ASTRIDE]
    float* Bs = sh + 2 * A_STAGE;      // 2 stages of [BK][BSTRIDE]

    const int tid  = threadIdx.x;
    const int lane = tid & 31;
    const int wid  = tid >> 5;
    const int wm   = wid >> 2;         // 0..1  (64-row slab)
    const int wn   = wid & 3;          // 0..3  (32-col slab)
    const int lr   = lane >> 2;        // 0..7
    const int lc   = lane & 3;         // 0..3

    const float* Ab = A + (size_t)blockIdx.y * BM * lda;
    const float* Bb = Bg + (size_t)blockIdx.x * BN;

    float acc[4][4][4];
    #pragma unroll
    for (int i = 0; i < 4; i++)
        #pragma unroll
        for (int j = 0; j < 4; j++)
            #pragma unroll
            for (int r = 0; r < 4; r++) acc[i][j][r] = 0.f;

    const int niter = K / BK;

    // ---- tile loaders (all shapes divide evenly; no predicates) ----
    auto loadA = [&](int it, int st) {
        const float* src = Ab + it * BK;
        float* dst = As + st * A_STAGE;
        #pragma unroll
        for (int j = 0; j < 4; j++) {
            int idx = tid + j * 256;            // 0..1023
            int r = idx >> 3;                   // row 0..127
            int c = (idx & 7) << 2;             // col 0,4..28
            cpasync16(dst + r * ASTRIDE + c, src + (size_t)r * lda + c);
        }
    };
    auto loadB = [&](int it, int st) {
        const float* src = Bb + (size_t)(it * BK) * ldb;
        float* dst = Bs + st * B_STAGE;
        #pragma unroll
        for (int j = 0; j < 4; j++) {
            int idx = tid + j * 256;
            int r = idx >> 5;                   // k row 0..31
            int c = (idx & 31) << 2;            // n col 0,4..124
            cpasync16(dst + r * BSTRIDE + c, src + (size_t)r * ldb + c);
        }
    };

    loadA(0, 0); loadB(0, 0);
    asm volatile("cp.async.commit_group;\n");

    for (int it = 0; it < niter; ++it) {
        int st = it & 1;
        asm volatile("cp.async.wait_group 0;\n");
        __syncthreads();
        if (it + 1 < niter) { loadA(it + 1, st ^ 1); loadB(it + 1, st ^ 1); }
        asm volatile("cp.async.commit_group;\n");

        const float* Aa = As + st * A_STAGE + (wm * 64) * ASTRIDE;
        const float* Bw = Bs + st * B_STAGE + wn * 32;

        #pragma unroll
        for (int ks = 0; ks < 4; ks++) {
            const int k = ks * 8 + lc;
            uint32_t a[4][4], b[4][2];
            #pragma unroll
            for (int mf = 0; mf < 4; mf++) {
                const float* ap = Aa + (mf * 16 + lr) * ASTRIDE + k;
                a[mf][0] = f2tf32(ap[0]);
                a[mf][1] = f2tf32(ap[8 * ASTRIDE]);
                a[mf][2] = f2tf32(ap[4]);
                a[mf][3] = f2tf32(ap[8 * ASTRIDE + 4]);
            }
            #pragma unroll
            for (int nf = 0; nf < 4; nf++) {
                const float* bp = Bw + k * BSTRIDE + nf * 8 + lr;
                b[nf][0] = f2tf32(bp[0]);
                b[nf][1] = f2tf32(bp[4 * BSTRIDE]);
            }
            #pragma unroll
            for (int mf = 0; mf < 4; mf++)
                #pragma unroll
                for (int nf = 0; nf < 4; nf++) {
                    asm volatile(
                        "mma.sync.aligned.m16n8k8.row.col.f32.tf32.tf32.f32 "
                        "{%0,%1,%2,%3}, {%4,%5,%6,%7}, {%8,%9}, {%0,%1,%2,%3};\n"
                        : "+f"(acc[mf][nf][0]), "+f"(acc[mf][nf][1]),
                          "+f"(acc[mf][nf][2]), "+f"(acc[mf][nf][3])
                        : "r"(a[mf][0]), "r"(a[mf][1]), "r"(a[mf][2]), "r"(a[mf][3]),
                          "r"(b[nf][0]), "r"(b[nf][1]));
                }
        }
        __syncthreads();
    }

    // ---- epilogue: bias + relu + scale, float2 stores ----
    const int rowBase = blockIdx.y * BM + wm * 64 + lr;
    const int colBase = blockIdx.x * BN + wn * 32 + lc * 2;
    #pragma unroll
    for (int mf = 0; mf < 4; mf++) {
        #pragma unroll
        for (int nf = 0; nf < 4; nf++) {
            int r0 = rowBase + mf * 16;
            int c0 = colBase + nf * 8;
            float b0 = bias ? bias[c0]     : 0.f;
            float b1 = bias ? bias[c0 + 1] : 0.f;
            float v0 = acc[mf][nf][0] + b0;
            float v1 = acc[mf][nf][1] + b1;
            float v2 = acc[mf][nf][2] + b0;
            float v3 = acc[mf][nf][3] + b1;
            if (doRelu) {
                v0 = fmaxf(v0, 0.f); v1 = fmaxf(v1, 0.f);
                v2 = fmaxf(v2, 0.f); v3 = fmaxf(v3, 0.f);
            }
            float2 lo = make_float2(v0 * scale, v1 * scale);
            float2 hi = make_float2(v2 * scale, v3 * scale);
            *(float2*)(C + (size_t)r0 * ldc + c0)       = lo;
            *(float2*)(C + (size_t)(r0 + 8) * ldc + c0) = hi;
        }
    }
}

// ---------------- chunked prefix scan of Yh over t ---------------------------
__global__ void k_chunksum() {
    int g = blockIdx.x * blockDim.x + threadIdx.x;      // 65536 threads
    int h = g % H_;
    int c = (g / H_) % NCHUNK;
    int b = g / (H_ * NCHUNK);
    const float* base = g_yh + ((size_t)(b * T_ + c * CHLEN)) * H_ + h;
    float s = 0.f;
    #pragma unroll 8
    for (int j = 0; j < CHLEN; j++) s += base[(size_t)j * H_];
    g_csum[(b * NCHUNK + c) * H_ + h] = s;
}

__global__ void k_scan() {
    int g = blockIdx.x * blockDim.x + threadIdx.x;      // 2048 threads
    int h = g % H_;
    int b = g / H_;
    float run = 0.f;
    #pragma unroll
    for (int c = 0; c < NCHUNK; c++) {
        int idx = (b * NCHUNK + c) * H_ + h;
        float t = g_csum[idx];
        g_csum[idx] = run;
        run += t;
    }
}

__global__ void k_hist(const float* __restrict__ bh) {
    int g = blockIdx.x * blockDim.x + threadIdx.x;      // 65536 threads
    int h = g % H_;
    int c = (g / H_) % NCHUNK;
    int b = g / (H_ * NCHUNK);
    float excl = g_csum[(b * NCHUNK + c) * H_ + h];
    float bias = bh[h];
    #pragma unroll 4
    for (int j = 0; j < CHLEN; j++) {
        int t = c * CHLEN + j;
        float y = g_yh[((size_t)(b * T_ + t)) * H_ + h];
        float val = (t == 0) ? y : excl / (float)t;
        excl += y;
        float o = fmaxf(val + bias, 0.f);
        g_merged[((size_t)(b * T_ + t)) * (2 * H_) + H_ + h] = o;
    }
}

// ---------------- LayerNorm over H=1024 per row -------------------------------
__global__ __launch_bounds__(256) void k_ln(const float* __restrict__ X,
                                            const float* __restrict__ w,
                                            const float* __restrict__ b,
                                            float* __restrict__ Y)
{
    int row = blockIdx.x;
    int tid = threadIdx.x;                 // 256 threads * 4 elems = 1024
    const float* x = X + (size_t)row * H_;
    float4 v = ((const float4*)x)[tid];
    float s  = v.x + v.y + v.z + v.w;
    float sq = v.x * v.x + v.y * v.y + v.z * v.z + v.w * v.w;

    __shared__ float sh[2][8];
    #pragma unroll
    for (int o = 16; o; o >>= 1) {
        s  += __shfl_xor_sync(0xffffffffu, s, o);
        sq += __shfl_xor_sync(0xffffffffu, sq, o);
    }
    if ((tid & 31) == 0) { sh[0][tid >> 5] = s; sh[1][tid >> 5] = sq; }
    __syncthreads();
    if (tid < 32) {
        s  = (tid < 8) ? sh[0][tid] : 0.f;
        sq = (tid < 8) ? sh[1][tid] : 0.f;
        #pragma unroll
        for (int o = 4; o; o >>= 1) {
            s  += __shfl_xor_sync(0xffffffffu, s, o);
            sq += __shfl_xor_sync(0xffffffffu, sq, o);
        }
        if (tid == 0) { sh[0][0] = s; sh[1][0] = sq; }
    }
    __syncthreads();
    float mu   = sh[0][0] * (1.f / H_);
    float var  = sh[1][0] * (1.f / H_) - mu * mu;
    float rstd = rsqrtf(var + 1e-5f);

    float4 wv = ((const float4*)w)[tid];
    float4 bv = ((const float4*)b)[tid];
    float4 o;
    o.x = (v.x - mu) * rstd * wv.x + bv.x;
    o.y = (v.y - mu) * rstd * wv.y + bv.y;
    o.z = (v.z - mu) * rstd * wv.z + bv.z;
    o.w = (v.w - mu) * rstd * wv.w + bv.w;
    ((float4*)(Y + (size_t)row * H_))[tid] = o;
}

// ---------------- launch ------------------------------------------------------
extern "C" void kernel_launch(void* const* d_in, const int* in_sizes, int n_in,
                              void* d_out, int out_size)
{
    const int*   tokens = (const int*)  d_in[0];
    const float* E    = (const float*)d_in[1];
    const float* Wc   = (const float*)d_in[2];
    const float* bc   = (const float*)d_in[3];
    const float* Wh   = (const float*)d_in[4];
    const float* bh   = (const float*)d_in[5];
    const float* Wm   = (const float*)d_in[6];
    const float* bm   = (const float*)d_in[7];
    const float* Wo   = (const float*)d_in[8];
    const float* bo   = (const float*)d_in[9];
    const float* ln_w = (const float*)d_in[10];
    const float* ln_b = (const float*)d_in[11];
    float* out = (float*)d_out;

    float *emb, *yh, *merged, *normed;
    cudaGetSymbolAddress((void**)&emb,    g_emb);
    cudaGetSymbolAddress((void**)&yh,     g_yh);
    cudaGetSymbolAddress((void**)&merged, g_merged);
    cudaGetSymbolAddress((void**)&normed, g_normed);

    // allow 70KB dynamic smem (idempotent; not a stream op, capture-safe)
    cudaFuncSetAttribute(tf32gemm, cudaFuncAttributeMaxDynamicSharedMemorySize,
                         SMEM_BYTES);

    // 1) gather embeddings
    k_embed<<<(BT_ * D_ / 4) / 256, 256>>>(tokens, E);

    // 2) cur_enc = relu(emb@Wc + bc) -> left half of g_merged (ldc = 2H)
    tf32gemm<<<dim3(H_ / BN, BT_ / BM), 256, SMEM_BYTES>>>(
        emb, Wc, merged, D_, D_, H_, 2 * H_, bc, 1, 1.f);

    // 3) Yh = emb@Wh (no epilogue)
    tf32gemm<<<dim3(H_ / BN, BT_ / BM), 256, SMEM_BYTES>>>(
        emb, Wh, yh, D_, D_, H_, H_, nullptr, 0, 1.f);

    // 4-6) hist_enc = relu(cumsum(Yh)/count + bh) -> right half of g_merged
    k_chunksum<<<(B_ * NCHUNK * H_) / 256, 256>>>();
    k_scan<<<(B_ * H_) / 256, 256>>>();
    k_hist<<<(B_ * NCHUNK * H_) / 256, 256>>>(bh);

    // 7) merged2 = relu(merged@Wm + bm)  (K=2048) -> reuse g_yh
    tf32gemm<<<dim3(H_ / BN, BT_ / BM), 256, SMEM_BYTES>>>(
        merged, Wm, yh, 2 * H_, 2 * H_, H_, H_, bm, 1, 1.f);

    // 8) layernorm
    k_ln<<<BT_, 256>>>(yh, ln_w, ln_b, normed);

    // 9) logits = (normed@Wo + bo) * 0.1   (268 GF, the dominant GEMM)
    tf32gemm<<<dim3(V_ / BN, BT_ / BM), 256, SMEM_BYTES>>>(
        normed, Wo, out, H_, H_, V_, V_, bo, 0, 0.1f);
}

// round 11
// speedup vs baseline: 3.4403x; 1.0615x over previous
#include <cuda_runtime.h>
#include <cstdint>

#define B_ 2
#define T_ 2048
#define D_ 512
#define H_ 1024
#define V_ 32000
#define BT_ (B_*T_)
#define NCHUNK 32
#define CHLEN (T_/NCHUNK)   /* 64 */

// ---------------- scratch (static device globals; no allocs allowed) ----------
__device__ __align__(1024) float g_emb[BT_ * D_];          // tf32-rounded
__device__ __align__(1024) float g_yh[BT_ * H_];           // fp32; later merged2
__device__ __align__(1024) float g_merged[BT_ * 2 * H_];   // tf32-rounded
__device__ __align__(1024) float g_normed[BT_ * H_];       // tf32-rounded
__device__ __align__(1024) float g_csum[B_ * NCHUNK * H_];
__device__ __align__(1024) float g_wcT[H_ * D_];           // K-major, rounded
__device__ __align__(1024) float g_whT[H_ * D_];
__device__ __align__(1024) float g_wmT[H_ * 2 * H_];
__device__ __align__(1024) float g_woT[(size_t)V_ * H_];   // 131 MB

// ---------------- helpers ------------------------------------------------------
__device__ __forceinline__ float round_tf32(float x) {
    uint32_t u; asm("cvt.rna.tf32.f32 %0, %1;" : "=r"(u) : "f"(x));
    return __uint_as_float(u);
}
__device__ __forceinline__ uint32_t smem_u32(const void* p) {
    return (uint32_t)__cvta_generic_to_shared(p);
}
__device__ __forceinline__ void cpasync16(void* s, const void* g) {
    asm volatile("cp.async.cg.shared.global [%0], [%1], 16;\n"
                 :: "r"(smem_u32(s)), "l"(g));
}

// =================== tf32 mma.sync GEMM (R4-proven instruction set) ===========
// C[M,N] = epi(A[M,K] @ Bt[N,K]^T). CTA tile 128x256, 256 thr (8 warps 2x4),
// warp tile 64x64, m16n8k8.tf32, operands PRE-ROUNDED to tf32 (no in-loop cvt).
// smem: A[128][36] + B[256][36] per stage (row-major, K-contig), 3 stages.
#define BMt 128
#define BNt 256
#define KCt 32
#define RS 36                               /* row stride in floats */
#define A_FLOATS (BMt * RS)                 /* 4608 */
#define B_FLOATS (BNt * RS)                 /* 9216 */
#define STAGE_FLOATS (A_FLOATS + B_FLOATS)  /* 13824 */
#define NSTAGE 3
#define TC_SMEM (NSTAGE * STAGE_FLOATS * 4) /* 165888 */

__global__ __launch_bounds__(256, 1) void tc_gemm(
    const float* __restrict__ A, const float* __restrict__ Bt,
    float* __restrict__ C, int K, int ldc,
    const float* __restrict__ bias, int doRelu, float scale, int roundOut)
{
    extern __shared__ float sh[];

    const int tid  = threadIdx.x;
    const int wid  = tid >> 5;
    const int lane = tid & 31;
    const int wm   = wid >> 2;          // 0..1 (64-row slab)
    const int wn   = wid & 3;           // 0..3 (64-col slab)
    const int lr   = lane >> 2;         // 0..7
    const int lc   = lane & 3;          // 0..3
    const int niter = K / KCt;

    const float* Ab = A  + (size_t)blockIdx.y * BMt * K;
    const float* Bb = Bt + (size_t)blockIdx.x * BNt * K;

    float acc[4][8][4];
    #pragma unroll
    for (int i = 0; i < 4; i++)
        #pragma unroll
        for (int j = 0; j < 8; j++)
            #pragma unroll
            for (int r = 0; r < 4; r++) acc[i][j][r] = 0.f;

    auto loadStage = [&](int chunk, int st) {
        float* sA = sh + st * STAGE_FLOATS;
        float* sB = sA + A_FLOATS;
        const int k0 = chunk * KCt;
        #pragma unroll
        for (int j = 0; j < 4; j++) {              // A: 128 rows x 8 pieces
            int idx = tid + j * 256;
            int r = idx >> 3, p = idx & 7;
            cpasync16(sA + r * RS + p * 4, Ab + (size_t)r * K + k0 + p * 4);
        }
        #pragma unroll
        for (int j = 0; j < 8; j++) {              // B: 256 rows x 8 pieces
            int idx = tid + j * 256;
            int r = idx >> 3, p = idx & 7;
            cpasync16(sB + r * RS + p * 4, Bb + (size_t)r * K + k0 + p * 4);
        }
        asm volatile("cp.async.commit_group;");
    };

    // prologue: 2 stages in flight
    loadStage(0, 0);
    if (niter > 1) loadStage(1, 1); else asm volatile("cp.async.commit_group;");

    for (int i = 0; i < niter; i++) {
        const int st = i % NSTAGE;
        asm volatile("cp.async.wait_group 1;");
        __syncthreads();

        const uint32_t* Aw = (const uint32_t*)(sh + st * STAGE_FLOATS) + (wm * 64) * RS;
        const uint32_t* Bw = (const uint32_t*)(sh + st * STAGE_FLOATS + A_FLOATS) + (wn * 64) * RS;

        #pragma unroll
        for (int ks = 0; ks < 4; ks++) {
            const int k = ks * 8 + lc;
            uint32_t a[4][4], b[8][2];
            #pragma unroll
            for (int mf = 0; mf < 4; mf++) {
                const uint32_t* ap = Aw + (mf * 16 + lr) * RS + k;
                a[mf][0] = ap[0];
                a[mf][1] = ap[8 * RS];
                a[mf][2] = ap[4];
                a[mf][3] = ap[8 * RS + 4];
            }
            #pragma unroll
            for (int nf = 0; nf < 8; nf++) {
                const uint32_t* bp = Bw + (nf * 8 + lr) * RS + k;
                b[nf][0] = bp[0];
                b[nf][1] = bp[4];
            }
            #pragma unroll
            for (int mf = 0; mf < 4; mf++)
                #pragma unroll
                for (int nf = 0; nf < 8; nf++) {
                    asm volatile(
                        "mma.sync.aligned.m16n8k8.row.col.f32.tf32.tf32.f32 "
                        "{%0,%1,%2,%3}, {%4,%5,%6,%7}, {%8,%9}, {%0,%1,%2,%3};\n"
                        : "+f"(acc[mf][nf][0]), "+f"(acc[mf][nf][1]),
                          "+f"(acc[mf][nf][2]), "+f"(acc[mf][nf][3])
                        : "r"(a[mf][0]), "r"(a[mf][1]), "r"(a[mf][2]), "r"(a[mf][3]),
                          "r"(b[nf][0]), "r"(b[nf][1]));
                }
        }
        __syncthreads();                 // everyone done reading stage st
        if (i + 2 < niter) loadStage(i + 2, (i + 2) % NSTAGE);
        else asm volatile("cp.async.commit_group;");   // keep group count invariant
    }

    // ---- epilogue: bias + relu + scale (+tf32 round), float2 stores ----
    const int rowBase = blockIdx.y * BMt + wm * 64 + lr;
    const int colBase = blockIdx.x * BNt + wn * 64 + lc * 2;
    #pragma unroll
    for (int mf = 0; mf < 4; mf++) {
        #pragma unroll
        for (int nf = 0; nf < 8; nf++) {
            int r0 = rowBase + mf * 16;
            int c0 = colBase + nf * 8;
            float b0 = bias ? bias[c0]     : 0.f;
            float b1 = bias ? bias[c0 + 1] : 0.f;
            float v0 = acc[mf][nf][0] + b0;
            float v1 = acc[mf][nf][1] + b1;
            float v2 = acc[mf][nf][2] + b0;
            float v3 = acc[mf][nf][3] + b1;
            if (doRelu) {
                v0 = fmaxf(v0, 0.f); v1 = fmaxf(v1, 0.f);
                v2 = fmaxf(v2, 0.f); v3 = fmaxf(v3, 0.f);
            }
            v0 *= scale; v1 *= scale; v2 *= scale; v3 *= scale;
            if (roundOut) {
                v0 = round_tf32(v0); v1 = round_tf32(v1);
                v2 = round_tf32(v2); v3 = round_tf32(v3);
            }
            *(float2*)(C + (size_t)r0 * ldc + c0)       = make_float2(v0, v1);
            *(float2*)(C + (size_t)(r0 + 8) * ldc + c0) = make_float2(v2, v3);
        }
    }
}

// ---------------- weight transpose [R,C] -> [C,R], tf32-rounded ---------------
__global__ void k_transpose(const float* __restrict__ S, float* __restrict__ Dd,
                            int R, int Cc)
{
    __shared__ float t[32][33];
    int c0 = blockIdx.x * 32, r0 = blockIdx.y * 32;
    int x = threadIdx.x, y = threadIdx.y;   // 32 x 8
    #pragma unroll
    for (int k = 0; k < 32; k += 8)
        t[y + k][x] = S[(size_t)(r0 + y + k) * Cc + c0 + x];
    __syncthreads();
    #pragma unroll
    for (int k = 0; k < 32; k += 8)
        Dd[(size_t)(c0 + y + k) * R + r0 + x] = round_tf32(t[x][y + k]);
}

// ---------------- embedding gather (tf32-rounded) ------------------------------
__global__ void k_embed(const int* __restrict__ tokens, const float* __restrict__ E) {
    int i = blockIdx.x * blockDim.x + threadIdx.x;      // over BT_*D_/4 float4s
    int row = i / (D_ / 4);
    int c4  = i % (D_ / 4);
    int tok = tokens[row];
    float4 v = ((const float4*)(E + (size_t)tok * D_))[c4];
    v.x = round_tf32(v.x); v.y = round_tf32(v.y);
    v.z = round_tf32(v.z); v.w = round_tf32(v.w);
    ((float4*)g_emb)[i] = v;
}

// ---------------- chunked prefix scan of Yh over t -----------------------------
__global__ void k_chunksum() {
    int g = blockIdx.x * blockDim.x + threadIdx.x;
    int h = g % H_;
    int c = (g / H_) % NCHUNK;
    int b = g / (H_ * NCHUNK);
    const float* base = g_yh + ((size_t)(b * T_ + c * CHLEN)) * H_ + h;
    float s = 0.f;
    #pragma unroll 8
    for (int j = 0; j < CHLEN; j++) s += base[(size_t)j * H_];
    g_csum[(b * NCHUNK + c) * H_ + h] = s;
}

__global__ void k_scan() {
    int g = blockIdx.x * blockDim.x + threadIdx.x;
    int h = g % H_;
    int b = g / H_;
    float run = 0.f;
    #pragma unroll
    for (int c = 0; c < NCHUNK; c++) {
        int idx = (b * NCHUNK + c) * H_ + h;
        float t = g_csum[idx];
        g_csum[idx] = run;
        run += t;
    }
}

__global__ void k_hist(const float* __restrict__ bh) {
    int g = blockIdx.x * blockDim.x + threadIdx.x;
    int h = g % H_;
    int c = (g / H_) % NCHUNK;
    int b = g / (H_ * NCHUNK);
    float excl = g_csum[(b * NCHUNK + c) * H_ + h];
    float bias = bh[h];
    #pragma unroll 4
    for (int j = 0; j < CHLEN; j++) {
        int t = c * CHLEN + j;
        float y = g_yh[((size_t)(b * T_ + t)) * H_ + h];
        float val = (t == 0) ? y : excl / (float)t;
        excl += y;
        float o = round_tf32(fmaxf(val + bias, 0.f));
        g_merged[((size_t)(b * T_ + t)) * (2 * H_) + H_ + h] = o;
    }
}

// ---------------- LayerNorm over H=1024 per row (tf32-rounded out) -------------
__global__ __launch_bounds__(256) void k_ln(const float* __restrict__ X,
                                            const float* __restrict__ w,
                                            const float* __restrict__ b,
                                            float* __restrict__ Y)
{
    int row = blockIdx.x;
    int tid = threadIdx.x;
    const float* x = X + (size_t)row * H_;
    float4 v = ((const float4*)x)[tid];
    float s  = v.x + v.y + v.z + v.w;
    float sq = v.x * v.x + v.y * v.y + v.z * v.z + v.w * v.w;

    __shared__ float sh[2][8];
    #pragma unroll
    for (int o = 16; o; o >>= 1) {
        s  += __shfl_xor_sync(0xffffffffu, s, o);
        sq += __shfl_xor_sync(0xffffffffu, sq, o);
    }
    if ((tid & 31) == 0) { sh[0][tid >> 5] = s; sh[1][tid >> 5] = sq; }
    __syncthreads();
    if (tid < 32) {
        s  = (tid < 8) ? sh[0][tid] : 0.f;
        sq = (tid < 8) ? sh[1][tid] : 0.f;
        #pragma unroll
        for (int o = 4; o; o >>= 1) {
            s  += __shfl_xor_sync(0xffffffffu, s, o);
            sq += __shfl_xor_sync(0xffffffffu, sq, o);
        }
        if (tid == 0) { sh[0][0] = s; sh[1][0] = sq; }
    }
    __syncthreads();
    float mu   = sh[0][0] * (1.f / H_);
    float var  = sh[1][0] * (1.f / H_) - mu * mu;
    float rstd = rsqrtf(var + 1e-5f);

    float4 wv = ((const float4*)w)[tid];
    float4 bv = ((const float4*)b)[tid];
    float4 o;
    o.x = round_tf32((v.x - mu) * rstd * wv.x + bv.x);
    o.y = round_tf32((v.y - mu) * rstd * wv.y + bv.y);
    o.z = round_tf32((v.z - mu) * rstd * wv.z + bv.z);
    o.w = round_tf32((v.w - mu) * rstd * wv.w + bv.w);
    ((float4*)(Y + (size_t)row * H_))[tid] = o;
}

// ---------------- launch --------------------------------------------------------
extern "C" void kernel_launch(void* const* d_in, const int* in_sizes, int n_in,
                              void* d_out, int out_size)
{
    const int*   tokens = (const int*)  d_in[0];
    const float* E    = (const float*)d_in[1];
    const float* Wc   = (const float*)d_in[2];
    const float* bc   = (const float*)d_in[3];
    const float* Wh   = (const float*)d_in[4];
    const float* bh   = (const float*)d_in[5];
    const float* Wm   = (const float*)d_in[6];
    const float* bm   = (const float*)d_in[7];
    const float* Wo   = (const float*)d_in[8];
    const float* bo   = (const float*)d_in[9];
    const float* ln_w = (const float*)d_in[10];
    const float* ln_b = (const float*)d_in[11];
    float* out = (float*)d_out;

    float *emb, *yh, *merged, *normed, *wcT, *whT, *wmT, *woT;
    cudaGetSymbolAddress((void**)&emb,    g_emb);
    cudaGetSymbolAddress((void**)&yh,     g_yh);
    cudaGetSymbolAddress((void**)&merged, g_merged);
    cudaGetSymbolAddress((void**)&normed, g_normed);
    cudaGetSymbolAddress((void**)&wcT,    g_wcT);
    cudaGetSymbolAddress((void**)&whT,    g_whT);
    cudaGetSymbolAddress((void**)&wmT,    g_wmT);
    cudaGetSymbolAddress((void**)&woT,    g_woT);

    cudaFuncSetAttribute(tc_gemm, cudaFuncAttributeMaxDynamicSharedMemorySize,
                         TC_SMEM);

    dim3 tb(32, 8);
    // weight transposes -> K-major, tf32-rounded
    k_transpose<<<dim3(H_ / 32,  D_ / 32),     tb>>>(Wc, wcT, D_,     H_);
    k_transpose<<<dim3(H_ / 32,  D_ / 32),     tb>>>(Wh, whT, D_,     H_);
    k_transpose<<<dim3(H_ / 32,  2 * H_ / 32), tb>>>(Wm, wmT, 2 * H_, H_);
    k_transpose<<<dim3(V_ / 32,  H_ / 32),     tb>>>(Wo, woT, H_,     V_);

    // 1) gather embeddings (tf32-rounded)
    k_embed<<<(BT_ * D_ / 4) / 256, 256>>>(tokens, E);

    // 2) cur_enc = relu(emb@Wc + bc) -> left half of g_merged (ldc=2H, rounded)
    tc_gemm<<<dim3(H_ / BNt, BT_ / BMt), 256, TC_SMEM>>>(
        emb, wcT, merged, D_, 2 * H_, bc, 1, 1.f, 1);

    // 3) Yh = emb@Wh (raw fp32 out; rounding happens in k_hist)
    tc_gemm<<<dim3(H_ / BNt, BT_ / BMt), 256, TC_SMEM>>>(
        emb, whT, yh, D_, H_, nullptr, 0, 1.f, 0);

    // 4-6) hist_enc = relu(cumsum(Yh)/count + bh) -> right half of g_merged
    k_chunksum<<<(B_ * NCHUNK * H_) / 256, 256>>>();
    k_scan<<<(B_ * H_) / 256, 256>>>();
    k_hist<<<(B_ * NCHUNK * H_) / 256, 256>>>(bh);

    // 7) merged2 = relu(merged@Wm + bm) (K=2048) -> g_yh (LN input, raw fp32)
    tc_gemm<<<dim3(H_ / BNt, BT_ / BMt), 256, TC_SMEM>>>(
        merged, wmT, yh, 2 * H_, H_, bm, 1, 1.f, 0);

    // 8) layernorm (tf32-rounded out)
    k_ln<<<BT_, 256>>>(yh, ln_w, ln_b, normed);

    // 9) logits = (normed@Wo + bo) * 0.1  (268 GF dominant GEMM)
    tc_gemm<<<dim3(V_ / BNt, BT_ / BMt), 256, TC_SMEM>>>(
        normed, woT, out, H_, V_, bo, 0, 0.1f, 0);
}

// round 13
// speedup vs baseline: 3.8211x; 1.1107x over previous
#include <cuda_runtime.h>
#include <cstdint>

#define B_ 2
#define T_ 2048
#define D_ 512
#define H_ 1024
#define V_ 32000
#define BT_ (B_*T_)
#define NCHUNK 32
#define CHLEN (T_/NCHUNK)   /* 64 */

// ---------------- scratch (static device globals; no allocs allowed) ----------
__device__ __align__(1024) float g_emb[BT_ * D_];          // tf32-rounded
__device__ __align__(1024) float g_yh[BT_ * H_];           // fp32; later merged2
__device__ __align__(1024) float g_merged[BT_ * 2 * H_];   // tf32-rounded
__device__ __align__(1024) float g_normed[BT_ * H_];       // tf32-rounded
__device__ __align__(1024) float g_csum[B_ * NCHUNK * H_];
__device__ __align__(1024) float g_wcT[H_ * D_];           // K-major, rounded
__device__ __align__(1024) float g_whT[H_ * D_];
__device__ __align__(1024) float g_wmT[H_ * 2 * H_];
__device__ __align__(1024) float g_woT[(size_t)V_ * H_];   // 131 MB

// ---------------- helpers ------------------------------------------------------
__device__ __forceinline__ float round_tf32(float x) {
    uint32_t u; asm("cvt.rna.tf32.f32 %0, %1;" : "=r"(u) : "f"(x));
    return __uint_as_float(u);
}
__device__ __forceinline__ uint32_t smem_u32(const void* p) {
    return (uint32_t)__cvta_generic_to_shared(p);
}
__device__ __forceinline__ void cpasync16(void* s, const void* g) {
    asm volatile("cp.async.cg.shared.global [%0], [%1], 16;\n"
                 :: "r"(smem_u32(s)), "l"(g));
}

// =================== tf32 mma.sync GEMM (R11-proven, single-sync mainloop) ====
// C[M,N] = epi(A[M,K] @ Bt[N,K]^T). CTA tile 128x256, 256 thr (8 warps 2x4),
// warp tile 64x64, m16n8k8.tf32, operands pre-rounded to tf32.
// smem: A[128][36] + B[256][36] per stage, 4 stages (221KB), ONE syncthreads
// per K-chunk (stage i+3 == stage i-1, already released by the top-of-loop
// sync), wait_group 2 decouples loads from compute.
#define BMt 128
#define BNt 256
#define KCt 32
#define RS 36                               /* row stride in floats */
#define A_FLOATS (BMt * RS)                 /* 4608 */
#define B_FLOATS (BNt * RS)                 /* 9216 */
#define STAGE_FLOATS (A_FLOATS + B_FLOATS)  /* 13824 */
#define NSTAGE 4
#define TC_SMEM (NSTAGE * STAGE_FLOATS * 4) /* 221184 */

__global__ __launch_bounds__(256, 1) void tc_gemm(
    const float* __restrict__ A, const float* __restrict__ Bt,
    float* __restrict__ C, int K, int ldc,
    const float* __restrict__ bias, int doRelu, float scale, int roundOut)
{
    extern __shared__ float sh[];

    const int tid  = threadIdx.x;
    const int wid  = tid >> 5;
    const int lane = tid & 31;
    const int wm   = wid >> 2;          // 0..1 (64-row slab)
    const int wn   = wid & 3;           // 0..3 (64-col slab)
    const int lr   = lane >> 2;         // 0..7
    const int lc   = lane & 3;          // 0..3
    const int niter = K / KCt;          // >= 16 for all our GEMMs

    const float* Ab = A  + (size_t)blockIdx.y * BMt * K;
    const float* Bb = Bt + (size_t)blockIdx.x * BNt * K;

    float acc[4][8][4];
    #pragma unroll
    for (int i = 0; i < 4; i++)
        #pragma unroll
        for (int j = 0; j < 8; j++)
            #pragma unroll
            for (int r = 0; r < 4; r++) acc[i][j][r] = 0.f;

    auto loadStage = [&](int chunk, int st) {
        float* sA = sh + st * STAGE_FLOATS;
        float* sB = sA + A_FLOATS;
        const int k0 = chunk * KCt;
        #pragma unroll
        for (int j = 0; j < 4; j++) {              // A: 128 rows x 8 pieces
            int idx = tid + j * 256;
            int r = idx >> 3, p = idx & 7;
            cpasync16(sA + r * RS + p * 4, Ab + (size_t)r * K + k0 + p * 4);
        }
        #pragma unroll
        for (int j = 0; j < 8; j++) {              // B: 256 rows x 8 pieces
            int idx = tid + j * 256;
            int r = idx >> 3, p = idx & 7;
            cpasync16(sB + r * RS + p * 4, Bb + (size_t)r * K + k0 + p * 4);
        }
    };

    // prologue: 3 stages in flight (niter >= 16 > 3 always here)
    loadStage(0, 0); asm volatile("cp.async.commit_group;");
    loadStage(1, 1); asm volatile("cp.async.commit_group;");
    loadStage(2, 2); asm volatile("cp.async.commit_group;");

    for (int i = 0; i < niter; i++) {
        const int st = i & (NSTAGE - 1);
        // 3+i groups committed; <=2 pending => chunks 0..i have landed.
        asm volatile("cp.async.wait_group 2;");
        __syncthreads();   // all warps done with compute i-1 (stage (i+3)&3)

        const uint32_t* Aw = (const uint32_t*)(sh + st * STAGE_FLOATS) + (wm * 64) * RS;
        const uint32_t* Bw = (const uint32_t*)(sh + st * STAGE_FLOATS + A_FLOATS) + (wn * 64) * RS;

        #pragma unroll
        for (int ks = 0; ks < 4; ks++) {
            const int k = ks * 8 + lc;
            uint32_t a[4][4], b[8][2];
            #pragma unroll
            for (int mf = 0; mf < 4; mf++) {
                const uint32_t* ap = Aw + (mf * 16 + lr) * RS + k;
                a[mf][0] = ap[0];
                a[mf][1] = ap[8 * RS];
                a[mf][2] = ap[4];
                a[mf][3] = ap[8 * RS + 4];
            }
            #pragma unroll
            for (int nf = 0; nf < 8; nf++) {
                const uint32_t* bp = Bw + (nf * 8 + lr) * RS + k;
                b[nf][0] = bp[0];
                b[nf][1] = bp[4];
            }
            #pragma unroll
            for (int mf = 0; mf < 4; mf++)
                #pragma unroll
                for (int nf = 0; nf < 8; nf++) {
                    asm volatile(
                        "mma.sync.aligned.m16n8k8.row.col.f32.tf32.tf32.f32 "
                        "{%0,%1,%2,%3}, {%4,%5,%6,%7}, {%8,%9}, {%0,%1,%2,%3};\n"
                        : "+f"(acc[mf][nf][0]), "+f"(acc[mf][nf][1]),
                          "+f"(acc[mf][nf][2]), "+f"(acc[mf][nf][3])
                        : "r"(a[mf][0]), "r"(a[mf][1]), "r"(a[mf][2]), "r"(a[mf][3]),
                          "r"(b[nf][0]), "r"(b[nf][1]));
                }
        }

        // load chunk i+3 into stage (i+3)&3 == (i-1)&3, released by the sync above
        if (i + 3 < niter) loadStage(i + 3, (i + 3) & (NSTAGE - 1));
        asm volatile("cp.async.commit_group;");   // exactly one group per iter
    }

    // ---- epilogue: bias + relu + scale (+tf32 round), float2 stores ----
    const int rowBase = blockIdx.y * BMt + wm * 64 + lr;
    const int colBase = blockIdx.x * BNt + wn * 64 + lc * 2;
    #pragma unroll
    for (int mf = 0; mf < 4; mf++) {
        #pragma unroll
        for (int nf = 0; nf < 8; nf++) {
            int r0 = rowBase + mf * 16;
            int c0 = colBase + nf * 8;
            float b0 = bias ? bias[c0]     : 0.f;
            float b1 = bias ? bias[c0 + 1] : 0.f;
            float v0 = acc[mf][nf][0] + b0;
            float v1 = acc[mf][nf][1] + b1;
            float v2 = acc[mf][nf][2] + b0;
            float v3 = acc[mf][nf][3] + b1;
            if (doRelu) {
                v0 = fmaxf(v0, 0.f); v1 = fmaxf(v1, 0.f);
                v2 = fmaxf(v2, 0.f); v3 = fmaxf(v3, 0.f);
            }
            v0 *= scale; v1 *= scale; v2 *= scale; v3 *= scale;
            if (roundOut) {
                v0 = round_tf32(v0); v1 = round_tf32(v1);
                v2 = round_tf32(v2); v3 = round_tf32(v3);
            }
            *(float2*)(C + (size_t)r0 * ldc + c0)       = make_float2(v0, v1);
            *(float2*)(C + (size_t)(r0 + 8) * ldc + c0) = make_float2(v2, v3);
        }
    }
}

// ---------------- weight transpose [R,C] -> [C,R], tf32-rounded ---------------
__global__ void k_transpose(const float* __restrict__ S, float* __restrict__ Dd,
                            int R, int Cc)
{
    __shared__ float t[32][33];
    int c0 = blockIdx.x * 32, r0 = blockIdx.y * 32;
    int x = threadIdx.x, y = threadIdx.y;   // 32 x 8
    #pragma unroll
    for (int k = 0; k < 32; k += 8)
        t[y + k][x] = S[(size_t)(r0 + y + k) * Cc + c0 + x];
    __syncthreads();
    #pragma unroll
    for (int k = 0; k < 32; k += 8)
        Dd[(size_t)(c0 + y + k) * R + r0 + x] = round_tf32(t[x][y + k]);
}

// ---------------- embedding gather (tf32-rounded) ------------------------------
__global__ void k_embed(const int* __restrict__ tokens, const float* __restrict__ E) {
    int i = blockIdx.x * blockDim.x + threadIdx.x;      // over BT_*D_/4 float4s
    int row = i / (D_ / 4);
    int c4  = i % (D_ / 4);
    int tok = tokens[row];
    float4 v = ((const float4*)(E + (size_t)tok * D_))[c4];
    v.x = round_tf32(v.x); v.y = round_tf32(v.y);
    v.z = round_tf32(v.z); v.w = round_tf32(v.w);
    ((float4*)g_emb)[i] = v;
}

// ---------------- chunked prefix scan of Yh over t -----------------------------
__global__ void k_chunksum() {
    int g = blockIdx.x * blockDim.x + threadIdx.x;
    int h = g % H_;
    int c = (g / H_) % NCHUNK;
    int b = g / (H_ * NCHUNK);
    const float* base = g_yh + ((size_t)(b * T_ + c * CHLEN)) * H_ + h;
    float s = 0.f;
    #pragma unroll 8
    for (int j = 0; j < CHLEN; j++) s += base[(size_t)j * H_];
    g_csum[(b * NCHUNK + c) * H_ + h] = s;
}

__global__ void k_scan() {
    int g = blockIdx.x * blockDim.x + threadIdx.x;
    int h = g % H_;
    int b = g / H_;
    float run = 0.f;
    #pragma unroll
    for (int c = 0; c < NCHUNK; c++) {
        int idx = (b * NCHUNK + c) * H_ + h;
        float t = g_csum[idx];
        g_csum[idx] = run;
        run += t;
    }
}

__global__ void k_hist(const float* __restrict__ bh) {
    int g = blockIdx.x * blockDim.x + threadIdx.x;
    int h = g % H_;
    int c = (g / H_) % NCHUNK;
    int b = g / (H_ * NCHUNK);
    float excl = g_csum[(b * NCHUNK + c) * H_ + h];
    float bias = bh[h];
    #pragma unroll 4
    for (int j = 0; j < CHLEN; j++) {
        int t = c * CHLEN + j;
        float y = g_yh[((size_t)(b * T_ + t)) * H_ + h];
        float val = (t == 0) ? y : excl / (float)t;
        excl += y;
        float o = round_tf32(fmaxf(val + bias, 0.f));
        g_merged[((size_t)(b * T_ + t)) * (2 * H_) + H_ + h] = o;
    }
}

// ---------------- LayerNorm over H=1024 per row (tf32-rounded out) -------------
__global__ __launch_bounds__(256) void k_ln(const float* __restrict__ X,
                                            const float* __restrict__ w,
                                            const float* __restrict__ b,
                                            float* __restrict__ Y)
{
    int row = blockIdx.x;
    int tid = threadIdx.x;
    const float* x = X + (size_t)row * H_;
    float4 v = ((const float4*)x)[tid];
    float s  = v.x + v.y + v.z + v.w;
    float sq = v.x * v.x + v.y * v.y + v.z * v.z + v.w * v.w;

    __shared__ float sh[2][8];
    #pragma unroll
    for (int o = 16; o; o >>= 1) {
        s  += __shfl_xor_sync(0xffffffffu, s, o);
        sq += __shfl_xor_sync(0xffffffffu, sq, o);
    }
    if ((tid & 31) == 0) { sh[0][tid >> 5] = s; sh[1][tid >> 5] = sq; }
    __syncthreads();
    if (tid < 32) {
        s  = (tid < 8) ? sh[0][tid] : 0.f;
        sq = (tid < 8) ? sh[1][tid] : 0.f;
        #pragma unroll
        for (int o = 4; o; o >>= 1) {
            s  += __shfl_xor_sync(0xffffffffu, s, o);
            sq += __shfl_xor_sync(0xffffffffu, sq, o);
        }
        if (tid == 0) { sh[0][0] = s; sh[1][0] = sq; }
    }
    __syncthreads();
    float mu   = sh[0][0] * (1.f / H_);
    float var  = sh[1][0] * (1.f / H_) - mu * mu;
    float rstd = rsqrtf(var + 1e-5f);

    float4 wv = ((const float4*)w)[tid];
    float4 bv = ((const float4*)b)[tid];
    float4 o;
    o.x = round_tf32((v.x - mu) * rstd * wv.x + bv.x);
    o.y = round_tf32((v.y - mu) * rstd * wv.y + bv.y);
    o.z = round_tf32((v.z - mu) * rstd * wv.z + bv.z);
    o.w = round_tf32((v.w - mu) * rstd * wv.w + bv.w);
    ((float4*)(Y + (size_t)row * H_))[tid] = o;
}

// ---------------- launch --------------------------------------------------------
extern "C" void kernel_launch(void* const* d_in, const int* in_sizes, int n_in,
                              void* d_out, int out_size)
{
    const int*   tokens = (const int*)  d_in[0];
    const float* E    = (const float*)d_in[1];
    const float* Wc   = (const float*)d_in[2];
    const float* bc   = (const float*)d_in[3];
    const float* Wh   = (const float*)d_in[4];
    const float* bh   = (const float*)d_in[5];
    const float* Wm   = (const float*)d_in[6];
    const float* bm   = (const float*)d_in[7];
    const float* Wo   = (const float*)d_in[8];
    const float* bo   = (const float*)d_in[9];
    const float* ln_w = (const float*)d_in[10];
    const float* ln_b = (const float*)d_in[11];
    float* out = (float*)d_out;

    float *emb, *yh, *merged, *normed, *wcT, *whT, *wmT, *woT;
    cudaGetSymbolAddress((void**)&emb,    g_emb);
    cudaGetSymbolAddress((void**)&yh,     g_yh);
    cudaGetSymbolAddress((void**)&merged, g_merged);
    cudaGetSymbolAddress((void**)&normed, g_normed);
    cudaGetSymbolAddress((void**)&wcT,    g_wcT);
    cudaGetSymbolAddress((void**)&whT,    g_whT);
    cudaGetSymbolAddress((void**)&wmT,    g_wmT);
    cudaGetSymbolAddress((void**)&woT,    g_woT);

    cudaFuncSetAttribute(tc_gemm, cudaFuncAttributeMaxDynamicSharedMemorySize,
                         TC_SMEM);

    dim3 tb(32, 8);
    // weight transposes -> K-major, tf32-rounded
    k_transpose<<<dim3(H_ / 32,  D_ / 32),     tb>>>(Wc, wcT, D_,     H_);
    k_transpose<<<dim3(H_ / 32,  D_ / 32),     tb>>>(Wh, whT, D_,     H_);
    k_transpose<<<dim3(H_ / 32,  2 * H_ / 32), tb>>>(Wm, wmT, 2 * H_, H_);
    k_transpose<<<dim3(V_ / 32,  H_ / 32),     tb>>>(Wo, woT, H_,     V_);

    // 1) gather embeddings (tf32-rounded)
    k_embed<<<(BT_ * D_ / 4) / 256, 256>>>(tokens, E);

    // 2) cur_enc = relu(emb@Wc + bc) -> left half of g_merged (ldc=2H, rounded)
    tc_gemm<<<dim3(H_ / BNt, BT_ / BMt), 256, TC_SMEM>>>(
        emb, wcT, merged, D_, 2 * H_, bc, 1, 1.f, 1);

    // 3) Yh = emb@Wh (raw fp32 out; rounding happens in k_hist)
    tc_gemm<<<dim3(H_ / BNt, BT_ / BMt), 256, TC_SMEM>>>(
        emb, whT, yh, D_, H_, nullptr, 0, 1.f, 0);

    // 4-6) hist_enc = relu(cumsum(Yh)/count + bh) -> right half of g_merged
    k_chunksum<<<(B_ * NCHUNK * H_) / 256, 256>>>();
    k_scan<<<(B_ * H_) / 256, 256>>>();
    k_hist<<<(B_ * NCHUNK * H_) / 256, 256>>>(bh);

    // 7) merged2 = relu(merged@Wm + bm) (K=2048) -> g_yh (LN input, raw fp32)
    tc_gemm<<<dim3(H_ / BNt, BT_ / BMt), 256, TC_SMEM>>>(
        merged, wmT, yh, 2 * H_, H_, bm, 1, 1.f, 0);

    // 8) layernorm (tf32-rounded out)
    k_ln<<<BT_, 256>>>(yh, ln_w, ln_b, normed);

    // 9) logits = (normed@Wo + bo) * 0.1  (268 GF dominant GEMM)
    tc_gemm<<<dim3(V_ / BNt, BT_ / BMt), 256, TC_SMEM>>>(
        normed, woT, out, H_, V_, bo, 0, 0.1f, 0);
}

// round 14
// speedup vs baseline: 3.8404x; 1.0051x over previous
#include <cuda_runtime.h>
#include <cstdint>

#define B_ 2
#define T_ 2048
#define D_ 512
#define H_ 1024
#define V_ 32000
#define BT_ (B_*T_)
#define NCHUNK 32
#define CHLEN (T_/NCHUNK)   /* 64 */

// ---------------- scratch (static device globals; no allocs allowed) ----------
__device__ __align__(1024) float g_emb[BT_ * D_];          // tf32-rounded
__device__ __align__(1024) float g_yh[BT_ * H_];           // fp32; later merged2
__device__ __align__(1024) float g_merged[BT_ * 2 * H_];   // tf32-rounded
__device__ __align__(1024) float g_normed[BT_ * H_];       // tf32-rounded
__device__ __align__(1024) float g_csum[B_ * NCHUNK * H_];
__device__ __align__(1024) float g_wcT[H_ * D_];           // K-major, rounded
__device__ __align__(1024) float g_whT[H_ * D_];
__device__ __align__(1024) float g_wmT[H_ * 2 * H_];
__device__ __align__(1024) float g_woT[(size_t)V_ * H_];   // 131 MB

// ---------------- helpers ------------------------------------------------------
__device__ __forceinline__ float round_tf32(float x) {
    uint32_t u; asm("cvt.rna.tf32.f32 %0, %1;" : "=r"(u) : "f"(x));
    return __uint_as_float(u);
}
__device__ __forceinline__ uint32_t smem_u32(const void* p) {
    return (uint32_t)__cvta_generic_to_shared(p);
}
__device__ __forceinline__ void cpasync16(void* s, const void* g) {
    asm volatile("cp.async.cg.shared.global [%0], [%1], 16;\n"
                 :: "r"(smem_u32(s)), "l"(g));
}

// =================== tf32 mma.sync GEMM — 2 CTAs/SM for latency hiding ========
// C[M,N] = epi(A[M,K] @ Bt[N,K]^T). CTA tile 128x128, 256 thr (8 warps 2x4),
// warp tile 64x32 (acc=64 regs -> two CTAs fit the register file).
// smem: A[128][36] + B[128][36] per stage, 3 stages = 110592 B -> 2 CTAs/SM.
// Single syncthreads per chunk; load i+2 targets stage (i+2)%3 == (i-1)%3,
// released by the top-of-loop sync. wait_group 1 (prologue 2 + 1/iter).
#define BMt 128
#define BNt 128
#define KCt 32
#define RS 36                               /* row stride in floats */
#define A_FLOATS (BMt * RS)                 /* 4608 */
#define B_FLOATS (BNt * RS)                 /* 4608 */
#define STAGE_FLOATS (A_FLOATS + B_FLOATS)  /* 9216 */
#define NSTAGE 3
#define TC_SMEM (NSTAGE * STAGE_FLOATS * 4) /* 110592 */

__global__ __launch_bounds__(256, 2) void tc_gemm(
    const float* __restrict__ A, const float* __restrict__ Bt,
    float* __restrict__ C, int K, int ldc,
    const float* __restrict__ bias, int doRelu, float scale, int roundOut)
{
    extern __shared__ float sh[];

    const int tid  = threadIdx.x;
    const int wid  = tid >> 5;
    const int lane = tid & 31;
    const int wm   = wid >> 2;          // 0..1 (64-row slab)
    const int wn   = wid & 3;           // 0..3 (32-col slab)
    const int lr   = lane >> 2;         // 0..7
    const int lc   = lane & 3;          // 0..3
    const int niter = K / KCt;          // >= 16 for all our GEMMs

    const float* Ab = A  + (size_t)blockIdx.y * BMt * K;
    const float* Bb = Bt + (size_t)blockIdx.x * BNt * K;

    float acc[4][4][4];
    #pragma unroll
    for (int i = 0; i < 4; i++)
        #pragma unroll
        for (int j = 0; j < 4; j++)
            #pragma unroll
            for (int r = 0; r < 4; r++) acc[i][j][r] = 0.f;

    auto loadStage = [&](int chunk, int st) {
        float* sA = sh + st * STAGE_FLOATS;
        float* sB = sA + A_FLOATS;
        const int k0 = chunk * KCt;
        #pragma unroll
        for (int j = 0; j < 4; j++) {              // A: 128 rows x 8 pieces
            int idx = tid + j * 256;
            int r = idx >> 3, p = idx & 7;
            cpasync16(sA + r * RS + p * 4, Ab + (size_t)r * K + k0 + p * 4);
        }
        #pragma unroll
        for (int j = 0; j < 4; j++) {              // B: 128 rows x 8 pieces
            int idx = tid + j * 256;
            int r = idx >> 3, p = idx & 7;
            cpasync16(sB + r * RS + p * 4, Bb + (size_t)r * K + k0 + p * 4);
        }
    };

    // prologue: 2 stages in flight
    loadStage(0, 0); asm volatile("cp.async.commit_group;");
    loadStage(1, 1); asm volatile("cp.async.commit_group;");

    int st = 0;
    for (int i = 0; i < niter; i++) {
        // 2+i groups committed; <=1 pending => chunks 0..i have landed.
        asm volatile("cp.async.wait_group 1;");
        __syncthreads();   // all warps done with compute i-1 (stage (i+2)%3)

        const uint32_t* Aw = (const uint32_t*)(sh + st * STAGE_FLOATS) + (wm * 64) * RS;
        const uint32_t* Bw = (const uint32_t*)(sh + st * STAGE_FLOATS + A_FLOATS) + (wn * 32) * RS;

        #pragma unroll
        for (int ks = 0; ks < 4; ks++) {
            const int k = ks * 8 + lc;
            uint32_t a[4][4], b[4][2];
            #pragma unroll
            for (int mf = 0; mf < 4; mf++) {
                const uint32_t* ap = Aw + (mf * 16 + lr) * RS + k;
                a[mf][0] = ap[0];
                a[mf][1] = ap[8 * RS];
                a[mf][2] = ap[4];
                a[mf][3] = ap[8 * RS + 4];
            }
            #pragma unroll
            for (int nf = 0; nf < 4; nf++) {
                const uint32_t* bp = Bw + (nf * 8 + lr) * RS + k;
                b[nf][0] = bp[0];
                b[nf][1] = bp[4];
            }
            #pragma unroll
            for (int mf = 0; mf < 4; mf++)
                #pragma unroll
                for (int nf = 0; nf < 4; nf++) {
                    asm volatile(
                        "mma.sync.aligned.m16n8k8.row.col.f32.tf32.tf32.f32 "
                        "{%0,%1,%2,%3}, {%4,%5,%6,%7}, {%8,%9}, {%0,%1,%2,%3};\n"
                        : "+f"(acc[mf][nf][0]), "+f"(acc[mf][nf][1]),
                          "+f"(acc[mf][nf][2]), "+f"(acc[mf][nf][3])
                        : "r"(a[mf][0]), "r"(a[mf][1]), "r"(a[mf][2]), "r"(a[mf][3]),
                          "r"(b[nf][0]), "r"(b[nf][1]));
                }
        }

        // load chunk i+2 into stage (i+2)%3 == (i-1)%3, released by sync above
        if (i + 2 < niter) loadStage(i + 2, (st + 2) % NSTAGE);
        asm volatile("cp.async.commit_group;");   // exactly one group per iter
        st = (st + 1) % NSTAGE;
    }

    // ---- epilogue: bias + relu + scale (+tf32 round), float2 stores ----
    const int rowBase = blockIdx.y * BMt + wm * 64 + lr;
    const int colBase = blockIdx.x * BNt + wn * 32 + lc * 2;
    #pragma unroll
    for (int mf = 0; mf < 4; mf++) {
        #pragma unroll
        for (int nf = 0; nf < 4; nf++) {
            int r0 = rowBase + mf * 16;
            int c0 = colBase + nf * 8;
            float b0 = bias ? bias[c0]     : 0.f;
            float b1 = bias ? bias[c0 + 1] : 0.f;
            float v0 = acc[mf][nf][0] + b0;
            float v1 = acc[mf][nf][1] + b1;
            float v2 = acc[mf][nf][2] + b0;
            float v3 = acc[mf][nf][3] + b1;
            if (doRelu) {
                v0 = fmaxf(v0, 0.f); v1 = fmaxf(v1, 0.f);
                v2 = fmaxf(v2, 0.f); v3 = fmaxf(v3, 0.f);
            }
            v0 *= scale; v1 *= scale; v2 *= scale; v3 *= scale;
            if (roundOut) {
                v0 = round_tf32(v0); v1 = round_tf32(v1);
                v2 = round_tf32(v2); v3 = round_tf32(v3);
            }
            *(float2*)(C + (size_t)r0 * ldc + c0)       = make_float2(v0, v1);
            *(float2*)(C + (size_t)(r0 + 8) * ldc + c0) = make_float2(v2, v3);
        }
    }
}

// ---------------- weight transpose [R,C] -> [C,R], tf32-rounded ---------------
__global__ void k_transpose(const float* __restrict__ S, float* __restrict__ Dd,
                            int R, int Cc)
{
    __shared__ float t[32][33];
    int c0 = blockIdx.x * 32, r0 = blockIdx.y * 32;
    int x = threadIdx.x, y = threadIdx.y;   // 32 x 8
    #pragma unroll
    for (int k = 0; k < 32; k += 8)
        t[y + k][x] = S[(size_t)(r0 + y + k) * Cc + c0 + x];
    __syncthreads();
    #pragma unroll
    for (int k = 0; k < 32; k += 8)
        Dd[(size_t)(c0 + y + k) * R + r0 + x] = round_tf32(t[x][y + k]);
}

// ---------------- embedding gather (tf32-rounded) ------------------------------
__global__ void k_embed(const int* __restrict__ tokens, const float* __restrict__ E) {
    int i = blockIdx.x * blockDim.x + threadIdx.x;      // over BT_*D_/4 float4s
    int row = i / (D_ / 4);
    int c4  = i % (D_ / 4);
    int tok = tokens[row];
    float4 v = ((const float4*)(E + (size_t)tok * D_))[c4];
    v.x = round_tf32(v.x); v.y = round_tf32(v.y);
    v.z = round_tf32(v.z); v.w = round_tf32(v.w);
    ((float4*)g_emb)[i] = v;
}

// ---------------- chunked prefix scan of Yh over t -----------------------------
__global__ void k_chunksum() {
    int g = blockIdx.x * blockDim.x + threadIdx.x;
    int h = g % H_;
    int c = (g / H_) % NCHUNK;
    int b = g / (H_ * NCHUNK);
    const float* base = g_yh + ((size_t)(b * T_ + c * CHLEN)) * H_ + h;
    float s = 0.f;
    #pragma unroll 8
    for (int j = 0; j < CHLEN; j++) s += base[(size_t)j * H_];
    g_csum[(b * NCHUNK + c) * H_ + h] = s;
}

__global__ void k_scan() {
    int g = blockIdx.x * blockDim.x + threadIdx.x;
    int h = g % H_;
    int b = g / H_;
    float run = 0.f;
    #pragma unroll
    for (int c = 0; c < NCHUNK; c++) {
        int idx = (b * NCHUNK + c) * H_ + h;
        float t = g_csum[idx];
        g_csum[idx] = run;
        run += t;
    }
}

__global__ void k_hist(const float* __restrict__ bh) {
    int g = blockIdx.x * blockDim.x + threadIdx.x;
    int h = g % H_;
    int c = (g / H_) % NCHUNK;
    int b = g / (H_ * NCHUNK);
    float excl = g_csum[(b * NCHUNK + c) * H_ + h];
    float bias = bh[h];
    #pragma unroll 4
    for (int j = 0; j < CHLEN; j++) {
        int t = c * CHLEN + j;
        float y = g_yh[((size_t)(b * T_ + t)) * H_ + h];
        float val = (t == 0) ? y : excl / (float)t;
        excl += y;
        float o = round_tf32(fmaxf(val + bias, 0.f));
        g_merged[((size_t)(b * T_ + t)) * (2 * H_) + H_ + h] = o;
    }
}

// ---------------- LayerNorm over H=1024 per row (tf32-rounded out) -------------
__global__ __launch_bounds__(256) void k_ln(const float* __restrict__ X,
                                            const float* __restrict__ w,
                                            const float* __restrict__ b,
                                            float* __restrict__ Y)
{
    int row = blockIdx.x;
    int tid = threadIdx.x;
    const float* x = X + (size_t)row * H_;
    float4 v = ((const float4*)x)[tid];
    float s  = v.x + v.y + v.z + v.w;
    float sq = v.x * v.x + v.y * v.y + v.z * v.z + v.w * v.w;

    __shared__ float sh[2][8];
    #pragma unroll
    for (int o = 16; o; o >>= 1) {
        s  += __shfl_xor_sync(0xffffffffu, s, o);
        sq += __shfl_xor_sync(0xffffffffu, sq, o);
    }
    if ((tid & 31) == 0) { sh[0][tid >> 5] = s; sh[1][tid >> 5] = sq; }
    __syncthreads();
    if (tid < 32) {
        s  = (tid < 8) ? sh[0][tid] : 0.f;
        sq = (tid < 8) ? sh[1][tid] : 0.f;
        #pragma unroll
        for (int o = 4; o; o >>= 1) {
            s  += __shfl_xor_sync(0xffffffffu, s, o);
            sq += __shfl_xor_sync(0xffffffffu, sq, o);
        }
        if (tid == 0) { sh[0][0] = s; sh[1][0] = sq; }
    }
    __syncthreads();
    float mu   = sh[0][0] * (1.f / H_);
    float var  = sh[1][0] * (1.f / H_) - mu * mu;
    float rstd = rsqrtf(var + 1e-5f);

    float4 wv = ((const float4*)w)[tid];
    float4 bv = ((const float4*)b)[tid];
    float4 o;
    o.x = round_tf32((v.x - mu) * rstd * wv.x + bv.x);
    o.y = round_tf32((v.y - mu) * rstd * wv.y + bv.y);
    o.z = round_tf32((v.z - mu) * rstd * wv.z + bv.z);
    o.w = round_tf32((v.w - mu) * rstd * wv.w + bv.w);
    ((float4*)(Y + (size_t)row * H_))[tid] = o;
}

// ---------------- launch --------------------------------------------------------
extern "C" void kernel_launch(void* const* d_in, const int* in_sizes, int n_in,
                              void* d_out, int out_size)
{
    const int*   tokens = (const int*)  d_in[0];
    const float* E    = (const float*)d_in[1];
    const float* Wc   = (const float*)d_in[2];
    const float* bc   = (const float*)d_in[3];
    const float* Wh   = (const float*)d_in[4];
    const float* bh   = (const float*)d_in[5];
    const float* Wm   = (const float*)d_in[6];
    const float* bm   = (const float*)d_in[7];
    const float* Wo   = (const float*)d_in[8];
    const float* bo   = (const float*)d_in[9];
    const float* ln_w = (const float*)d_in[10];
    const float* ln_b = (const float*)d_in[11];
    float* out = (float*)d_out;

    float *emb, *yh, *merged, *normed, *wcT, *whT, *wmT, *woT;
    cudaGetSymbolAddress((void**)&emb,    g_emb);
    cudaGetSymbolAddress((void**)&yh,     g_yh);
    cudaGetSymbolAddress((void**)&merged, g_merged);
    cudaGetSymbolAddress((void**)&normed, g_normed);
    cudaGetSymbolAddress((void**)&wcT,    g_wcT);
    cudaGetSymbolAddress((void**)&whT,    g_whT);
    cudaGetSymbolAddress((void**)&wmT,    g_wmT);
    cudaGetSymbolAddress((void**)&woT,    g_woT);

    cudaFuncSetAttribute(tc_gemm, cudaFuncAttributeMaxDynamicSharedMemorySize,
                         TC_SMEM);

    dim3 tb(32, 8);
    // weight transposes -> K-major, tf32-rounded
    k_transpose<<<dim3(H_ / 32,  D_ / 32),     tb>>>(Wc, wcT, D_,     H_);
    k_transpose<<<dim3(H_ / 32,  D_ / 32),     tb>>>(Wh, whT, D_,     H_);
    k_transpose<<<dim3(H_ / 32,  2 * H_ / 32), tb>>>(Wm, wmT, 2 * H_, H_);
    k_transpose<<<dim3(V_ / 32,  H_ / 32),     tb>>>(Wo, woT, H_,     V_);

    // 1) gather embeddings (tf32-rounded)
    k_embed<<<(BT_ * D_ / 4) / 256, 256>>>(tokens, E);

    // 2) cur_enc = relu(emb@Wc + bc) -> left half of g_merged (ldc=2H, rounded)
    tc_gemm<<<dim3(H_ / BNt, BT_ / BMt), 256, TC_SMEM>>>(
        emb, wcT, merged, D_, 2 * H_, bc, 1, 1.f, 1);

    // 3) Yh = emb@Wh (raw fp32 out; rounding happens in k_hist)
    tc_gemm<<<dim3(H_ / BNt, BT_ / BMt), 256, TC_SMEM>>>(
        emb, whT, yh, D_, H_, nullptr, 0, 1.f, 0);

    // 4-6) hist_enc = relu(cumsum(Yh)/count + bh) -> right half of g_merged
    k_chunksum<<<(B_ * NCHUNK * H_) / 256, 256>>>();
    k_scan<<<(B_ * H_) / 256, 256>>>();
    k_hist<<<(B_ * NCHUNK * H_) / 256, 256>>>(bh);

    // 7) merged2 = relu(merged@Wm + bm) (K=2048) -> g_yh (LN input, raw fp32)
    tc_gemm<<<dim3(H_ / BNt, BT_ / BMt), 256, TC_SMEM>>>(
        merged, wmT, yh, 2 * H_, H_, bm, 1, 1.f, 0);

    // 8) layernorm (tf32-rounded out)
    k_ln<<<BT_, 256>>>(yh, ln_w, ln_b, normed);

    // 9) logits = (normed@Wo + bo) * 0.1  (268 GF dominant GEMM)
    tc_gemm<<<dim3(V_ / BNt, BT_ / BMt), 256, TC_SMEM>>>(
        normed, woT, out, H_, V_, bo, 0, 0.1f, 0);
}

// round 15
// speedup vs baseline: 5.9568x; 1.5511x over previous
#include <cuda_runtime.h>
#include <cuda_fp16.h>
#include <cstdint>

#define B_ 2
#define T_ 2048
#define D_ 512
#define H_ 1024
#define V_ 32000
#define BT_ (B_*T_)
#define NCHUNK 32
#define CHLEN (T_/NCHUNK)   /* 64 */

// ---------------- scratch (static device globals; no allocs allowed) ----------
__device__ __align__(1024) __half g_embh[BT_ * D_];          // fp16 operands
__device__ __align__(1024) __half g_mergedh[BT_ * 2 * H_];
__device__ __align__(1024) __half g_normedh[BT_ * H_];
__device__ __align__(1024) float  g_yh[BT_ * H_];            // fp32 intermediates
__device__ __align__(1024) float  g_csum[B_ * NCHUNK * H_];
__device__ __align__(1024) __half g_wchT[H_ * D_];           // K-major fp16 weights
__device__ __align__(1024) __half g_whhT[H_ * D_];
__device__ __align__(1024) __half g_wmhT[H_ * 2 * H_];
__device__ __align__(1024) __half g_wohT[(size_t)V_ * H_];   // 65 MB (fits L2)

// ---------------- helpers ------------------------------------------------------
__device__ __forceinline__ uint32_t smem_u32(const void* p) {
    return (uint32_t)__cvta_generic_to_shared(p);
}
__device__ __forceinline__ void cpasync16(void* s, const void* g) {
    asm volatile("cp.async.cg.shared.global [%0], [%1], 16;\n"
                 :: "r"(smem_u32(s)), "l"(g));
}

// =================== fp16 mma.sync GEMM (m16n8k16, 2048 MACs/instr) ===========
// C[M,N] = epi(A[M,K] @ Bt[N,K]^T), A/Bt fp16 K-major, fp32 accumulate.
// CTA tile 128x256, 256 thr (8 warps 2x4), warp tile 64x64.
// smem rows padded to 40 halves (80B): fragment word-bank = (20*lr+lc)%32,
// all 32 unique -> conflict-free. 4 stages, single __syncthreads per chunk
// (R13-proven schedule: load i+3 targets stage (i-1)&3; wait_group 2).
#define BMt 128
#define BNt 256
#define KCt 32
#define RSH 40                              /* halves per smem row */
#define A_HALVES (BMt * RSH)                /* 5120 */
#define B_HALVES (BNt * RSH)                /* 10240 */
#define STAGE_HALVES (A_HALVES + B_HALVES)  /* 15360 */
#define NSTAGE 4
#define TC_SMEM (NSTAGE * STAGE_HALVES * 2) /* 122880 */

__global__ __launch_bounds__(256, 1) void tc_gemm(
    const __half* __restrict__ A, const __half* __restrict__ Bt,
    float* __restrict__ C, __half* __restrict__ Ch, int K, int ldc,
    const float* __restrict__ bias, int doRelu, float scale)
{
    extern __shared__ __half sh[];

    const int tid  = threadIdx.x;
    const int wid  = tid >> 5;
    const int lane = tid & 31;
    const int wm   = wid >> 2;          // 0..1 (64-row slab)
    const int wn   = wid & 3;           // 0..3 (64-col slab)
    const int lr   = lane >> 2;         // 0..7
    const int lc   = lane & 3;          // 0..3
    const int niter = K / KCt;          // >= 16 for all our GEMMs

    const __half* Ab = A  + (size_t)blockIdx.y * BMt * K;
    const __half* Bb = Bt + (size_t)blockIdx.x * BNt * K;

    float acc[4][8][4];
    #pragma unroll
    for (int i = 0; i < 4; i++)
        #pragma unroll
        for (int j = 0; j < 8; j++)
            #pragma unroll
            for (int r = 0; r < 4; r++) acc[i][j][r] = 0.f;

    auto loadStage = [&](int chunk, int st) {
        __half* sA = sh + st * STAGE_HALVES;
        __half* sB = sA + A_HALVES;
        const int k0 = chunk * KCt;
        #pragma unroll
        for (int j = 0; j < 2; j++) {              // A: 128 rows x 4 x 16B
            int idx = tid + j * 256;               // 0..511
            int r = idx >> 2, p = idx & 3;
            cpasync16(sA + r * RSH + p * 8, Ab + (size_t)r * K + k0 + p * 8);
        }
        #pragma unroll
        for (int j = 0; j < 4; j++) {              // B: 256 rows x 4 x 16B
            int idx = tid + j * 256;               // 0..1023
            int r = idx >> 2, p = idx & 3;
            cpasync16(sB + r * RSH + p * 8, Bb + (size_t)r * K + k0 + p * 8);
        }
    };

    // prologue: 3 stages in flight
    loadStage(0, 0); asm volatile("cp.async.commit_group;");
    loadStage(1, 1); asm volatile("cp.async.commit_group;");
    loadStage(2, 2); asm volatile("cp.async.commit_group;");

    for (int i = 0; i < niter; i++) {
        const int st = i & (NSTAGE - 1);
        // 3+i groups committed; <=2 pending => chunks 0..i have landed.
        asm volatile("cp.async.wait_group 2;");
        __syncthreads();   // all warps done with compute i-1 (stage (i+3)&3)

        const __half* Aw = sh + st * STAGE_HALVES + (wm * 64) * RSH;
        const __half* Bw = sh + st * STAGE_HALVES + A_HALVES + (wn * 64) * RSH;

        #pragma unroll
        for (int ks = 0; ks < 2; ks++) {           // 2 x K=16 per KC=32 chunk
            const int kh = ks * 16 + 2 * lc;       // half offset within chunk
            uint32_t a[4][4], b[8][2];
            #pragma unroll
            for (int mf = 0; mf < 4; mf++) {
                const __half* ap = Aw + (mf * 16 + lr) * RSH + kh;
                a[mf][0] = *(const uint32_t*)(ap);
                a[mf][1] = *(const uint32_t*)(ap + 8 * RSH);
                a[mf][2] = *(const uint32_t*)(ap + 8);
                a[mf][3] = *(const uint32_t*)(ap + 8 * RSH + 8);
            }
            #pragma unroll
            for (int nf = 0; nf < 8; nf++) {
                const __half* bp = Bw + (nf * 8 + lr) * RSH + kh;
                b[nf][0] = *(const uint32_t*)(bp);
                b[nf][1] = *(const uint32_t*)(bp + 8);
            }
            #pragma unroll
            for (int mf = 0; mf < 4; mf++)
                #pragma unroll
                for (int nf = 0; nf < 8; nf++) {
                    asm volatile(
                        "mma.sync.aligned.m16n8k16.row.col.f32.f16.f16.f32 "
                        "{%0,%1,%2,%3}, {%4,%5,%6,%7}, {%8,%9}, {%0,%1,%2,%3};\n"
                        : "+f"(acc[mf][nf][0]), "+f"(acc[mf][nf][1]),
                          "+f"(acc[mf][nf][2]), "+f"(acc[mf][nf][3])
                        : "r"(a[mf][0]), "r"(a[mf][1]), "r"(a[mf][2]), "r"(a[mf][3]),
                          "r"(b[nf][0]), "r"(b[nf][1]));
                }
        }

        // load chunk i+3 into stage (i+3)&3 == (i-1)&3, released by sync above
        if (i + 3 < niter) loadStage(i + 3, (i + 3) & (NSTAGE - 1));
        asm volatile("cp.async.commit_group;");   // exactly one group per iter
    }

    // ---- epilogue: bias + relu + scale; fp32 or fp16 stores ----
    const int rowBase = blockIdx.y * BMt + wm * 64 + lr;
    const int colBase = blockIdx.x * BNt + wn * 64 + lc * 2;
    #pragma unroll
    for (int mf = 0; mf < 4; mf++) {
        #pragma unroll
        for (int nf = 0; nf < 8; nf++) {
            int r0 = rowBase + mf * 16;
            int c0 = colBase + nf * 8;
            float b0 = bias ? bias[c0]     : 0.f;
            float b1 = bias ? bias[c0 + 1] : 0.f;
            float v0 = acc[mf][nf][0] + b0;
            float v1 = acc[mf][nf][1] + b1;
            float v2 = acc[mf][nf][2] + b0;
            float v3 = acc[mf][nf][3] + b1;
            if (doRelu) {
                v0 = fmaxf(v0, 0.f); v1 = fmaxf(v1, 0.f);
                v2 = fmaxf(v2, 0.f); v3 = fmaxf(v3, 0.f);
            }
            v0 *= scale; v1 *= scale; v2 *= scale; v3 *= scale;
            if (Ch) {
                *(__half2*)(Ch + (size_t)r0 * ldc + c0) =
                    __floats2half2_rn(v0, v1);
                *(__half2*)(Ch + (size_t)(r0 + 8) * ldc + c0) =
                    __floats2half2_rn(v2, v3);
            } else {
                *(float2*)(C + (size_t)r0 * ldc + c0)       = make_float2(v0, v1);
                *(float2*)(C + (size_t)(r0 + 8) * ldc + c0) = make_float2(v2, v3);
            }
        }
    }
}

// -------- weight transpose: S[R,C] fp32 -> D[C,R] fp16 (K-major) --------------
__global__ void k_transpose_h(const float* __restrict__ S, __half* __restrict__ Dd,
                              int R, int Cc)
{
    __shared__ float t[32][33];
    int c0 = blockIdx.x * 32, r0 = blockIdx.y * 32;
    int x = threadIdx.x, y = threadIdx.y;   // 32 x 8
    #pragma unroll
    for (int k = 0; k < 32; k += 8)
        t[y + k][x] = S[(size_t)(r0 + y + k) * Cc + c0 + x];
    __syncthreads();
    #pragma unroll
    for (int k = 0; k < 32; k += 8)
        Dd[(size_t)(c0 + y + k) * R + r0 + x] = __float2half_rn(t[x][y + k]);
}

// ---------------- embedding gather -> fp16 --------------------------------------
__global__ void k_embed(const int* __restrict__ tokens, const float* __restrict__ E) {
    int i = blockIdx.x * blockDim.x + threadIdx.x;      // over BT_*D_/4 float4s
    int row = i / (D_ / 4);
    int c4  = i % (D_ / 4);
    int tok = tokens[row];
    float4 v = ((const float4*)(E + (size_t)tok * D_))[c4];
    ((__half2*)g_embh)[i * 2]     = __floats2half2_rn(v.x, v.y);
    ((__half2*)g_embh)[i * 2 + 1] = __floats2half2_rn(v.z, v.w);
}

// ---------------- chunked prefix scan of Yh over t -----------------------------
__global__ void k_chunksum() {
    int g = blockIdx.x * blockDim.x + threadIdx.x;
    int h = g % H_;
    int c = (g / H_) % NCHUNK;
    int b = g / (H_ * NCHUNK);
    const float* base = g_yh + ((size_t)(b * T_ + c * CHLEN)) * H_ + h;
    float s = 0.f;
    #pragma unroll 8
    for (int j = 0; j < CHLEN; j++) s += base[(size_t)j * H_];
    g_csum[(b * NCHUNK + c) * H_ + h] = s;
}

__global__ void k_scan() {
    int g = blockIdx.x * blockDim.x + threadIdx.x;
    int h = g % H_;
    int b = g / H_;
    float run = 0.f;
    #pragma unroll
    for (int c = 0; c < NCHUNK; c++) {
        int idx = (b * NCHUNK + c) * H_ + h;
        float t = g_csum[idx];
        g_csum[idx] = run;
        run += t;
    }
}

__global__ void k_hist(const float* __restrict__ bh) {
    int g = blockIdx.x * blockDim.x + threadIdx.x;
    int h = g % H_;
    int c = (g / H_) % NCHUNK;
    int b = g / (H_ * NCHUNK);
    float excl = g_csum[(b * NCHUNK + c) * H_ + h];
    float bias = bh[h];
    #pragma unroll 4
    for (int j = 0; j < CHLEN; j++) {
        int t = c * CHLEN + j;
        float y = g_yh[((size_t)(b * T_ + t)) * H_ + h];
        float val = (t == 0) ? y : excl / (float)t;
        excl += y;
        float o = fmaxf(val + bias, 0.f);
        g_mergedh[((size_t)(b * T_ + t)) * (2 * H_) + H_ + h] = __float2half_rn(o);
    }
}

// ---------------- LayerNorm over H=1024 per row -> fp16 out --------------------
__global__ __launch_bounds__(256) void k_ln(const float* __restrict__ X,
                                            const float* __restrict__ w,
                                            const float* __restrict__ b)
{
    int row = blockIdx.x;
    int tid = threadIdx.x;
    const float* x = X + (size_t)row * H_;
    float4 v = ((const float4*)x)[tid];
    float s  = v.x + v.y + v.z + v.w;
    float sq = v.x * v.x + v.y * v.y + v.z * v.z + v.w * v.w;

    __shared__ float sh[2][8];
    #pragma unroll
    for (int o = 16; o; o >>= 1) {
        s  += __shfl_xor_sync(0xffffffffu, s, o);
        sq += __shfl_xor_sync(0xffffffffu, sq, o);
    }
    if ((tid & 31) == 0) { sh[0][tid >> 5] = s; sh[1][tid >> 5] = sq; }
    __syncthreads();
    if (tid < 32) {
        s  = (tid < 8) ? sh[0][tid] : 0.f;
        sq = (tid < 8) ? sh[1][tid] : 0.f;
        #pragma unroll
        for (int o = 4; o; o >>= 1) {
            s  += __shfl_xor_sync(0xffffffffu, s, o);
            sq += __shfl_xor_sync(0xffffffffu, sq, o);
        }
        if (tid == 0) { sh[0][0] = s; sh[1][0] = sq; }
    }
    __syncthreads();
    float mu   = sh[0][0] * (1.f / H_);
    float var  = sh[1][0] * (1.f / H_) - mu * mu;
    float rstd = rsqrtf(var + 1e-5f);

    float4 wv = ((const float4*)w)[tid];
    float4 bv = ((const float4*)b)[tid];
    float o0 = (v.x - mu) * rstd * wv.x + bv.x;
    float o1 = (v.y - mu) * rstd * wv.y + bv.y;
    float o2 = (v.z - mu) * rstd * wv.z + bv.z;
    float o3 = (v.w - mu) * rstd * wv.w + bv.w;
    size_t base2 = ((size_t)row * H_) / 2 + tid * 2;
    ((__half2*)g_normedh)[base2]     = __floats2half2_rn(o0, o1);
    ((__half2*)g_normedh)[base2 + 1] = __floats2half2_rn(o2, o3);
}

// ---------------- launch --------------------------------------------------------
extern "C" void kernel_launch(void* const* d_in, const int* in_sizes, int n_in,
                              void* d_out, int out_size)
{
    const int*   tokens = (const int*)  d_in[0];
    const float* E    = (const float*)d_in[1];
    const float* Wc   = (const float*)d_in[2];
    const float* bc   = (const float*)d_in[3];
    const float* Wh   = (const float*)d_in[4];
    const float* bh   = (const float*)d_in[5];
    const float* Wm   = (const float*)d_in[6];
    const float* bm   = (const float*)d_in[7];
    const float* Wo   = (const float*)d_in[8];
    const float* bo   = (const float*)d_in[9];
    const float* ln_w = (const float*)d_in[10];
    const float* ln_b = (const float*)d_in[11];
    float* out = (float*)d_out;

    __half *embh, *mergedh, *normedh, *wchT, *whhT, *wmhT, *wohT;
    float *yh;
    cudaGetSymbolAddress((void**)&embh,    g_embh);
    cudaGetSymbolAddress((void**)&mergedh, g_mergedh);
    cudaGetSymbolAddress((void**)&normedh, g_normedh);
    cudaGetSymbolAddress((void**)&wchT,    g_wchT);
    cudaGetSymbolAddress((void**)&whhT,    g_whhT);
    cudaGetSymbolAddress((void**)&wmhT,    g_wmhT);
    cudaGetSymbolAddress((void**)&wohT,    g_wohT);
    cudaGetSymbolAddress((void**)&yh,      g_yh);

    cudaFuncSetAttribute(tc_gemm, cudaFuncAttributeMaxDynamicSharedMemorySize,
                         TC_SMEM);

    dim3 tb(32, 8);
    // weight transposes -> K-major fp16
    k_transpose_h<<<dim3(H_ / 32,  D_ / 32),     tb>>>(Wc, wchT, D_,     H_);
    k_transpose_h<<<dim3(H_ / 32,  D_ / 32),     tb>>>(Wh, whhT, D_,     H_);
    k_transpose_h<<<dim3(H_ / 32,  2 * H_ / 32), tb>>>(Wm, wmhT, 2 * H_, H_);
    k_transpose_h<<<dim3(V_ / 32,  H_ / 32),     tb>>>(Wo, wohT, H_,     V_);

    // 1) gather embeddings -> fp16
    k_embed<<<(BT_ * D_ / 4) / 256, 256>>>(tokens, E);

    // 2) cur_enc = relu(emb@Wc + bc) -> fp16 into merged left half (ldc=2H)
    tc_gemm<<<dim3(H_ / BNt, BT_ / BMt), 256, TC_SMEM>>>(
        embh, wchT, nullptr, mergedh, D_, 2 * H_, bc, 1, 1.f);

    // 3) Yh = emb@Wh -> fp32
    tc_gemm<<<dim3(H_ / BNt, BT_ / BMt), 256, TC_SMEM>>>(
        embh, whhT, yh, nullptr, D_, H_, nullptr, 0, 1.f);

    // 4-6) hist_enc = relu(cumsum(Yh)/count + bh) -> fp16 merged right half
    k_chunksum<<<(B_ * NCHUNK * H_) / 256, 256>>>();
    k_scan<<<(B_ * H_) / 256, 256>>>();
    k_hist<<<(B_ * NCHUNK * H_) / 256, 256>>>(bh);

    // 7) merged2 = relu(merged@Wm + bm) (K=2048) -> fp32 g_yh (LN input)
    tc_gemm<<<dim3(H_ / BNt, BT_ / BMt), 256, TC_SMEM>>>(
        mergedh, wmhT, yh, nullptr, 2 * H_, H_, bm, 1, 1.f);

    // 8) layernorm -> fp16 normed
    k_ln<<<BT_, 256>>>(yh, ln_w, ln_b);

    // 9) logits = (normed@Wo + bo) * 0.1  (268 GF dominant GEMM)
    tc_gemm<<<dim3(V_ / BNt, BT_ / BMt), 256, TC_SMEM>>>(
        normedh, wohT, out, nullptr, H_, V_, bo, 0, 0.1f);
}

// round 16
// speedup vs baseline: 6.2279x; 1.0455x over previous
#include <cuda_runtime.h>
#include <cuda_fp16.h>
#include <cstdint>

#define B_ 2
#define T_ 2048
#define D_ 512
#define H_ 1024
#define V_ 32000
#define BT_ (B_*T_)
#define NCHUNK 32
#define CHLEN (T_/NCHUNK)   /* 64 */

// ---------------- scratch (static device globals; no allocs allowed) ----------
__device__ __align__(1024) __half g_embh[BT_ * D_];          // fp16 operands
__device__ __align__(1024) __half g_mergedh[BT_ * 2 * H_];
__device__ __align__(1024) __half g_normedh[BT_ * H_];
__device__ __align__(1024) float  g_yh[BT_ * H_];            // fp32 intermediates
__device__ __align__(1024) float  g_csum[B_ * NCHUNK * H_];
__device__ __align__(1024) __half g_wchT[H_ * D_];           // K-major fp16 weights
__device__ __align__(1024) __half g_whhT[H_ * D_];
__device__ __align__(1024) __half g_wmhT[H_ * 2 * H_];
__device__ __align__(1024) __half g_wohT[(size_t)V_ * H_];   // 65 MB (fits L2)

// ---------------- helpers ------------------------------------------------------
__device__ __forceinline__ uint32_t smem_u32(const void* p) {
    return (uint32_t)__cvta_generic_to_shared(p);
}
__device__ __forceinline__ void cpasync16(void* s, const void* g) {
    asm volatile("cp.async.cg.shared.global [%0], [%1], 16;\n"
                 :: "r"(smem_u32(s)), "l"(g));
}
__device__ __forceinline__ void ldsm_x4(uint32_t& r0, uint32_t& r1,
                                        uint32_t& r2, uint32_t& r3, uint32_t addr) {
    asm volatile("ldmatrix.sync.aligned.m8n8.x4.shared.b16 {%0,%1,%2,%3}, [%4];"
                 : "=r"(r0), "=r"(r1), "=r"(r2), "=r"(r3) : "r"(addr));
}

// =================== fp16 mma.sync GEMM (m16n8k16 + ldmatrix) =================
// C[M,N] = epi(A[M,K] @ Bt[N,K]^T), A/Bt fp16 K-major, fp32 accumulate.
// CTA tile 128x256, 256 thr (8 warps 2x4), warp tile 64x64.
// smem rows padded to 40 halves (80B = 5 x 16B): ldmatrix 16B-chunk index
// (5r mod 8) hits all 8 chunks -> conflict-free. 4 stages, single
// __syncthreads per chunk (R13 schedule), fragments double-buffered over the
// two k16 steps: 16 LDSM issued up-front, 64 MMAs ride the scoreboard.
#define BMt 128
#define BNt 256
#define KCt 32
#define RSH 40                              /* halves per smem row */
#define A_HALVES (BMt * RSH)                /* 5120 */
#define B_HALVES (BNt * RSH)                /* 10240 */
#define STAGE_HALVES (A_HALVES + B_HALVES)  /* 15360 */
#define NSTAGE 4
#define TC_SMEM (NSTAGE * STAGE_HALVES * 2) /* 122880 */

__global__ __launch_bounds__(256, 1) void tc_gemm(
    const __half* __restrict__ A, const __half* __restrict__ Bt,
    float* __restrict__ C, __half* __restrict__ Ch, int K, int ldc,
    const float* __restrict__ bias, int doRelu, float scale)
{
    extern __shared__ __half sh[];

    const int tid  = threadIdx.x;
    const int wid  = tid >> 5;
    const int lane = tid & 31;
    const int wm   = wid >> 2;          // 0..1 (64-row slab)
    const int wn   = wid & 3;           // 0..3 (64-col slab)
    const int lr   = lane >> 2;         // 0..7
    const int lc   = lane & 3;          // 0..3
    const int niter = K / KCt;

    // ldmatrix per-lane address components (constant across chunks)
    const int aRow = (lane & 15);            // + mf*16
    const int aKof = (lane >> 4) * 8;        // k-halfblock select
    const int bQ   = lane & 7;
    const int bHs  = (lane >> 3) & 1;
    const int bNs  = lane >> 4;

    const __half* Ab = A  + (size_t)blockIdx.y * BMt * K;
    const __half* Bb = Bt + (size_t)blockIdx.x * BNt * K;

    float acc[4][8][4];
    #pragma unroll
    for (int i = 0; i < 4; i++)
        #pragma unroll
        for (int j = 0; j < 8; j++)
            #pragma unroll
            for (int r = 0; r < 4; r++) acc[i][j][r] = 0.f;

    auto loadStage = [&](int chunk, int st) {
        __half* sA = sh + st * STAGE_HALVES;
        __half* sB = sA + A_HALVES;
        const int k0 = chunk * KCt;
        #pragma unroll
        for (int j = 0; j < 2; j++) {              // A: 128 rows x 4 x 16B
            int idx = tid + j * 256;
            int r = idx >> 2, p = idx & 3;
            cpasync16(sA + r * RSH + p * 8, Ab + (size_t)r * K + k0 + p * 8);
        }
        #pragma unroll
        for (int j = 0; j < 4; j++) {              // B: 256 rows x 4 x 16B
            int idx = tid + j * 256;
            int r = idx >> 2, p = idx & 3;
            cpasync16(sB + r * RSH + p * 8, Bb + (size_t)r * K + k0 + p * 8);
        }
    };

    // prologue: 3 stages in flight
    loadStage(0, 0); asm volatile("cp.async.commit_group;");
    loadStage(1, 1); asm volatile("cp.async.commit_group;");
    loadStage(2, 2); asm volatile("cp.async.commit_group;");

    for (int i = 0; i < niter; i++) {
        const int st = i & (NSTAGE - 1);
        asm volatile("cp.async.wait_group 2;");
        __syncthreads();   // all warps done with compute i-1 (stage (i+3)&3)

        const __half* Aw = sh + st * STAGE_HALVES + (wm * 64) * RSH;
        const __half* Bw = sh + st * STAGE_HALVES + A_HALVES + (wn * 64) * RSH;

        // ---- issue ALL fragment loads for both k16 steps (16 LDSM) ----
        uint32_t a[2][4][4], b[2][8][2];
        #pragma unroll
        for (int ks = 0; ks < 2; ks++) {
            const int kh = ks * 16;
            #pragma unroll
            for (int mf = 0; mf < 4; mf++) {
                uint32_t ad = smem_u32(Aw + (mf * 16 + aRow) * RSH + kh + aKof);
                ldsm_x4(a[ks][mf][0], a[ks][mf][1], a[ks][mf][2], a[ks][mf][3], ad);
            }
            #pragma unroll
            for (int p = 0; p < 4; p++) {
                uint32_t bd = smem_u32(Bw + (p * 16 + bNs * 8 + bQ) * RSH + kh + bHs * 8);
                ldsm_x4(b[ks][2 * p][0], b[ks][2 * p][1],
                        b[ks][2 * p + 1][0], b[ks][2 * p + 1][1], bd);
            }
        }

        // ---- 64 MMAs (scoreboard overlaps with LDSM completion) ----
        #pragma unroll
        for (int ks = 0; ks < 2; ks++)
            #pragma unroll
            for (int mf = 0; mf < 4; mf++)
                #pragma unroll
                for (int nf = 0; nf < 8; nf++) {
                    asm volatile(
                        "mma.sync.aligned.m16n8k16.row.col.f32.f16.f16.f32 "
                        "{%0,%1,%2,%3}, {%4,%5,%6,%7}, {%8,%9}, {%0,%1,%2,%3};\n"
                        : "+f"(acc[mf][nf][0]), "+f"(acc[mf][nf][1]),
                          "+f"(acc[mf][nf][2]), "+f"(acc[mf][nf][3])
                        : "r"(a[ks][mf][0]), "r"(a[ks][mf][1]),
                          "r"(a[ks][mf][2]), "r"(a[ks][mf][3]),
                          "r"(b[ks][nf][0]), "r"(b[ks][nf][1]));
                }

        if (i + 3 < niter) loadStage(i + 3, (i + 3) & (NSTAGE - 1));
        asm volatile("cp.async.commit_group;");   // exactly one group per iter
    }

    // ---- epilogue: bias + relu + scale; fp32 or fp16 stores ----
    const int rowBase = blockIdx.y * BMt + wm * 64 + lr;
    const int colBase = blockIdx.x * BNt + wn * 64 + lc * 2;
    #pragma unroll
    for (int mf = 0; mf < 4; mf++) {
        #pragma unroll
        for (int nf = 0; nf < 8; nf++) {
            int r0 = rowBase + mf * 16;
            int c0 = colBase + nf * 8;
            float b0 = bias ? bias[c0]     : 0.f;
            float b1 = bias ? bias[c0 + 1] : 0.f;
            float v0 = acc[mf][nf][0] + b0;
            float v1 = acc[mf][nf][1] + b1;
            float v2 = acc[mf][nf][2] + b0;
            float v3 = acc[mf][nf][3] + b1;
            if (doRelu) {
                v0 = fmaxf(v0, 0.f); v1 = fmaxf(v1, 0.f);
                v2 = fmaxf(v2, 0.f); v3 = fmaxf(v3, 0.f);
            }
            v0 *= scale; v1 *= scale; v2 *= scale; v3 *= scale;
            if (Ch) {
                *(__half2*)(Ch + (size_t)r0 * ldc + c0) =
                    __floats2half2_rn(v0, v1);
                *(__half2*)(Ch + (size_t)(r0 + 8) * ldc + c0) =
                    __floats2half2_rn(v2, v3);
            } else {
                *(float2*)(C + (size_t)r0 * ldc + c0)       = make_float2(v0, v1);
                *(float2*)(C + (size_t)(r0 + 8) * ldc + c0) = make_float2(v2, v3);
            }
        }
    }
}

// -------- weight transpose: S[R,C] fp32 -> D[C,R] fp16 (K-major) --------------
__global__ void k_transpose_h(const float* __restrict__ S, __half* __restrict__ Dd,
                              int R, int Cc)
{
    __shared__ float t[32][33];
    int c0 = blockIdx.x * 32, r0 = blockIdx.y * 32;
    int x = threadIdx.x, y = threadIdx.y;   // 32 x 8
    #pragma unroll
    for (int k = 0; k < 32; k += 8)
        t[y + k][x] = S[(size_t)(r0 + y + k) * Cc + c0 + x];
    __syncthreads();
    #pragma unroll
    for (int k = 0; k < 32; k += 8)
        Dd[(size_t)(c0 + y + k) * R + r0 + x] = __float2half_rn(t[x][y + k]);
}

// ---------------- embedding gather -> fp16 --------------------------------------
__global__ void k_embed(const int* __restrict__ tokens, const float* __restrict__ E) {
    int i = blockIdx.x * blockDim.x + threadIdx.x;      // over BT_*D_/4 float4s
    int row = i / (D_ / 4);
    int c4  = i % (D_ / 4);
    int tok = tokens[row];
    float4 v = ((const float4*)(E + (size_t)tok * D_))[c4];
    ((__half2*)g_embh)[i * 2]     = __floats2half2_rn(v.x, v.y);
    ((__half2*)g_embh)[i * 2 + 1] = __floats2half2_rn(v.z, v.w);
}

// ---------------- chunked prefix scan of Yh over t -----------------------------
__global__ void k_chunksum() {
    int g = blockIdx.x * blockDim.x + threadIdx.x;
    int h = g % H_;
    int c = (g / H_) % NCHUNK;
    int b = g / (H_ * NCHUNK);
    const float* base = g_yh + ((size_t)(b * T_ + c * CHLEN)) * H_ + h;
    float s = 0.f;
    #pragma unroll 8
    for (int j = 0; j < CHLEN; j++) s += base[(size_t)j * H_];
    g_csum[(b * NCHUNK + c) * H_ + h] = s;
}

__global__ void k_scan() {
    int g = blockIdx.x * blockDim.x + threadIdx.x;
    int h = g % H_;
    int b = g / H_;
    float run = 0.f;
    #pragma unroll
    for (int c = 0; c < NCHUNK; c++) {
        int idx = (b * NCHUNK + c) * H_ + h;
        float t = g_csum[idx];
        g_csum[idx] = run;
        run += t;
    }
}

__global__ void k_hist(const float* __restrict__ bh) {
    int g = blockIdx.x * blockDim.x + threadIdx.x;
    int h = g % H_;
    int c = (g / H_) % NCHUNK;
    int b = g / (H_ * NCHUNK);
    float excl = g_csum[(b * NCHUNK + c) * H_ + h];
    float bias = bh[h];
    #pragma unroll 4
    for (int j = 0; j < CHLEN; j++) {
        int t = c * CHLEN + j;
        float y = g_yh[((size_t)(b * T_ + t)) * H_ + h];
        float val = (t == 0) ? y : excl / (float)t;
        excl += y;
        float o = fmaxf(val + bias, 0.f);
        g_mergedh[((size_t)(b * T_ + t)) * (2 * H_) + H_ + h] = __float2half_rn(o);
    }
}

// ---------------- LayerNorm over H=1024 per row -> fp16 out --------------------
__global__ __launch_bounds__(256) void k_ln(const float* __restrict__ X,
                                            const float* __restrict__ w,
                                            const float* __restrict__ b)
{
    int row = blockIdx.x;
    int tid = threadIdx.x;
    const float* x = X + (size_t)row * H_;
    float4 v = ((const float4*)x)[tid];
    float s  = v.x + v.y + v.z + v.w;
    float sq = v.x * v.x + v.y * v.y + v.z * v.z + v.w * v.w;

    __shared__ float sh[2][8];
    #pragma unroll
    for (int o = 16; o; o >>= 1) {
        s  += __shfl_xor_sync(0xffffffffu, s, o);
        sq += __shfl_xor_sync(0xffffffffu, sq, o);
    }
    if ((tid & 31) == 0) { sh[0][tid >> 5] = s; sh[1][tid >> 5] = sq; }
    __syncthreads();
    if (tid < 32) {
        s  = (tid < 8) ? sh[0][tid] : 0.f;
        sq = (tid < 8) ? sh[1][tid] : 0.f;
        #pragma unroll
        for (int o = 4; o; o >>= 1) {
            s  += __shfl_xor_sync(0xffffffffu, s, o);
            sq += __shfl_xor_sync(0xffffffffu, sq, o);
        }
        if (tid == 0) { sh[0][0] = s; sh[1][0] = sq; }
    }
    __syncthreads();
    float mu   = sh[0][0] * (1.f / H_);
    float var  = sh[1][0] * (1.f / H_) - mu * mu;
    float rstd = rsqrtf(var + 1e-5f);

    float4 wv = ((const float4*)w)[tid];
    float4 bv = ((const float4*)b)[tid];
    float o0 = (v.x - mu) * rstd * wv.x + bv.x;
    float o1 = (v.y - mu) * rstd * wv.y + bv.y;
    float o2 = (v.z - mu) * rstd * wv.z + bv.z;
    float o3 = (v.w - mu) * rstd * wv.w + bv.w;
    size_t base2 = ((size_t)row * H_) / 2 + tid * 2;
    ((__half2*)g_normedh)[base2]     = __floats2half2_rn(o0, o1);
    ((__half2*)g_normedh)[base2 + 1] = __floats2half2_rn(o2, o3);
}

// ---------------- launch --------------------------------------------------------
extern "C" void kernel_launch(void* const* d_in, const int* in_sizes, int n_in,
                              void* d_out, int out_size)
{
    const int*   tokens = (const int*)  d_in[0];
    const float* E    = (const float*)d_in[1];
    const float* Wc   = (const float*)d_in[2];
    const float* bc   = (const float*)d_in[3];
    const float* Wh   = (const float*)d_in[4];
    const float* bh   = (const float*)d_in[5];
    const float* Wm   = (const float*)d_in[6];
    const float* bm   = (const float*)d_in[7];
    const float* Wo   = (const float*)d_in[8];
    const float* bo   = (const float*)d_in[9];
    const float* ln_w = (const float*)d_in[10];
    const float* ln_b = (const float*)d_in[11];
    float* out = (float*)d_out;

    __half *embh, *mergedh, *normedh, *wchT, *whhT, *wmhT, *wohT;
    float *yh;
    cudaGetSymbolAddress((void**)&embh,    g_embh);
    cudaGetSymbolAddress((void**)&mergedh, g_mergedh);
    cudaGetSymbolAddress((void**)&normedh, g_normedh);
    cudaGetSymbolAddress((void**)&wchT,    g_wchT);
    cudaGetSymbolAddress((void**)&whhT,    g_whhT);
    cudaGetSymbolAddress((void**)&wmhT,    g_wmhT);
    cudaGetSymbolAddress((void**)&wohT,    g_wohT);
    cudaGetSymbolAddress((void**)&yh,      g_yh);

    cudaFuncSetAttribute(tc_gemm, cudaFuncAttributeMaxDynamicSharedMemorySize,
                         TC_SMEM);

    dim3 tb(32, 8);
    // weight transposes -> K-major fp16
    k_transpose_h<<<dim3(H_ / 32,  D_ / 32),     tb>>>(Wc, wchT, D_,     H_);
    k_transpose_h<<<dim3(H_ / 32,  D_ / 32),     tb>>>(Wh, whhT, D_,     H_);
    k_transpose_h<<<dim3(H_ / 32,  2 * H_ / 32), tb>>>(Wm, wmhT, 2 * H_, H_);
    k_transpose_h<<<dim3(V_ / 32,  H_ / 32),     tb>>>(Wo, wohT, H_,     V_);

    // 1) gather embeddings -> fp16
    k_embed<<<(BT_ * D_ / 4) / 256, 256>>>(tokens, E);

    // 2) cur_enc = relu(emb@Wc + bc) -> fp16 into merged left half (ldc=2H)
    tc_gemm<<<dim3(H_ / BNt, BT_ / BMt), 256, TC_SMEM>>>(
        embh, wchT, nullptr, mergedh, D_, 2 * H_, bc, 1, 1.f);

    // 3) Yh = emb@Wh -> fp32
    tc_gemm<<<dim3(H_ / BNt, BT_ / BMt), 256, TC_SMEM>>>(
        embh, whhT, yh, nullptr, D_, H_, nullptr, 0, 1.f);

    // 4-6) hist_enc = relu(cumsum(Yh)/count + bh) -> fp16 merged right half
    k_chunksum<<<(B_ * NCHUNK * H_) / 256, 256>>>();
    k_scan<<<(B_ * H_) / 256, 256>>>();
    k_hist<<<(B_ * NCHUNK * H_) / 256, 256>>>(bh);

    // 7) merged2 = relu(merged@Wm + bm) (K=2048) -> fp32 g_yh (LN input)
    tc_gemm<<<dim3(H_ / BNt, BT_ / BMt), 256, TC_SMEM>>>(
        mergedh, wmhT, yh, nullptr, 2 * H_, H_, bm, 1, 1.f);

    // 8) layernorm -> fp16 normed
    k_ln<<<BT_, 256>>>(yh, ln_w, ln_b);

    // 9) logits = (normed@Wo + bo) * 0.1  (268 GF dominant GEMM)
    tc_gemm<<<dim3(V_ / BNt, BT_ / BMt), 256, TC_SMEM>>>(
        normedh, wohT, out, nullptr, H_, V_, bo, 0, 0.1f);
}

// round 17
// speedup vs baseline: 6.9904x; 1.1224x over previous
#include <cuda_runtime.h>
#include <cuda_fp16.h>
#include <cstdint>

#define B_ 2
#define T_ 2048
#define D_ 512
#define H_ 1024
#define V_ 32000
#define BT_ (B_*T_)
#define NCHUNK 32
#define CHLEN (T_/NCHUNK)   /* 64 */

// ---------------- scratch (static device globals; no allocs allowed) ----------
__device__ __align__(1024) __half g_embh[BT_ * D_];          // fp16 operands
__device__ __align__(1024) __half g_mergedh[BT_ * 2 * H_];
__device__ __align__(1024) __half g_normedh[BT_ * H_];
__device__ __align__(1024) float  g_yh[BT_ * H_];            // fp32 intermediates
__device__ __align__(1024) float  g_csum[B_ * NCHUNK * H_];
__device__ __align__(1024) __half g_wchT[H_ * D_];           // K-major fp16 weights
__device__ __align__(1024) __half g_whhT[H_ * D_];
__device__ __align__(1024) __half g_wmhT[H_ * 2 * H_];
__device__ __align__(1024) __half g_wohT[(size_t)V_ * H_];   // 65 MB (fits L2)

// ---------------- helpers ------------------------------------------------------
__device__ __forceinline__ uint32_t smem_u32(const void* p) {
    return (uint32_t)__cvta_generic_to_shared(p);
}
__device__ __forceinline__ void cpasync16(void* s, const void* g) {
    asm volatile("cp.async.cg.shared.global [%0], [%1], 16;\n"
                 :: "r"(smem_u32(s)), "l"(g));
}
__device__ __forceinline__ void ldsm_x4(uint32_t& r0, uint32_t& r1,
                                        uint32_t& r2, uint32_t& r3, uint32_t addr) {
    asm volatile("ldmatrix.sync.aligned.m8n8.x4.shared.b16 {%0,%1,%2,%3}, [%4];"
                 : "=r"(r0), "=r"(r1), "=r"(r2), "=r"(r3) : "r"(addr));
}

// =================== fp16 mma.sync GEMM (m16n8k16 + ldmatrix, 2 CTAs/SM) ======
// C[M,N] = epi(A[M,K] @ Bt[N,K]^T), A/Bt fp16 K-major, fp32 accumulate.
// CTA tile 128x128, 256 thr (8 warps 2x4), warp tile 64x32, ~110 regs ->
// TWO CTAs co-resident per SM hide the per-chunk sync/epilogue bubbles that
// kept R16 at 79% of the HMMA ceiling. smem: rows padded to 40 halves
// (80B = 5x16B; ldmatrix chunk index 5r mod 8 covers all banks), 4 stages =
// 81920 B/CTA -> 2 CTAs = 164KB. R13 single-sync schedule (wait_group 2,
// load i+3 -> stage (i-1)&3).
#define BMt 128
#define BNt 128
#define KCt 32
#define RSH 40                              /* halves per smem row */
#define A_HALVES (BMt * RSH)                /* 5120 */
#define B_HALVES (BNt * RSH)                /* 5120 */
#define STAGE_HALVES (A_HALVES + B_HALVES)  /* 10240 */
#define NSTAGE 4
#define TC_SMEM (NSTAGE * STAGE_HALVES * 2) /* 81920 */

__global__ __launch_bounds__(256, 2) void tc_gemm(
    const __half* __restrict__ A, const __half* __restrict__ Bt,
    float* __restrict__ C, __half* __restrict__ Ch, int K, int ldc,
    const float* __restrict__ bias, int doRelu, float scale)
{
    extern __shared__ __half sh[];

    const int tid  = threadIdx.x;
    const int wid  = tid >> 5;
    const int lane = tid & 31;
    const int wm   = wid >> 2;          // 0..1 (64-row slab)
    const int wn   = wid & 3;           // 0..3 (32-col slab)
    const int lr   = lane >> 2;         // 0..7
    const int lc   = lane & 3;          // 0..3
    const int niter = K / KCt;

    // ldmatrix per-lane address components
    const int aRow = (lane & 15);            // + mf*16
    const int aKof = (lane >> 4) * 8;        // k-halfblock select
    const int bQ   = lane & 7;
    const int bHs  = (lane >> 3) & 1;
    const int bNs  = lane >> 4;

    const __half* Ab = A  + (size_t)blockIdx.y * BMt * K;
    const __half* Bb = Bt + (size_t)blockIdx.x * BNt * K;

    float acc[4][4][4];
    #pragma unroll
    for (int i = 0; i < 4; i++)
        #pragma unroll
        for (int j = 0; j < 4; j++)
            #pragma unroll
            for (int r = 0; r < 4; r++) acc[i][j][r] = 0.f;

    auto loadStage = [&](int chunk, int st) {
        __half* sA = sh + st * STAGE_HALVES;
        __half* sB = sA + A_HALVES;
        const int k0 = chunk * KCt;
        #pragma unroll
        for (int j = 0; j < 2; j++) {              // A: 128 rows x 4 x 16B
            int idx = tid + j * 256;
            int r = idx >> 2, p = idx & 3;
            cpasync16(sA + r * RSH + p * 8, Ab + (size_t)r * K + k0 + p * 8);
        }
        #pragma unroll
        for (int j = 0; j < 2; j++) {              // B: 128 rows x 4 x 16B
            int idx = tid + j * 256;
            int r = idx >> 2, p = idx & 3;
            cpasync16(sB + r * RSH + p * 8, Bb + (size_t)r * K + k0 + p * 8);
        }
    };

    // prologue: 3 stages in flight
    loadStage(0, 0); asm volatile("cp.async.commit_group;");
    loadStage(1, 1); asm volatile("cp.async.commit_group;");
    loadStage(2, 2); asm volatile("cp.async.commit_group;");

    for (int i = 0; i < niter; i++) {
        const int st = i & (NSTAGE - 1);
        asm volatile("cp.async.wait_group 2;");
        __syncthreads();   // all warps done with compute i-1 (stage (i+3)&3)

        const __half* Aw = sh + st * STAGE_HALVES + (wm * 64) * RSH;
        const __half* Bw = sh + st * STAGE_HALVES + A_HALVES + (wn * 32) * RSH;

        #pragma unroll
        for (int ks = 0; ks < 2; ks++) {
            const int kh = ks * 16;
            uint32_t a[4][4], b[4][2];
            #pragma unroll
            for (int mf = 0; mf < 4; mf++) {
                uint32_t ad = smem_u32(Aw + (mf * 16 + aRow) * RSH + kh + aKof);
                ldsm_x4(a[mf][0], a[mf][1], a[mf][2], a[mf][3], ad);
            }
            #pragma unroll
            for (int p = 0; p < 2; p++) {
                uint32_t bd = smem_u32(Bw + (p * 16 + bNs * 8 + bQ) * RSH + kh + bHs * 8);
                ldsm_x4(b[2 * p][0], b[2 * p][1], b[2 * p + 1][0], b[2 * p + 1][1], bd);
            }
            #pragma unroll
            for (int mf = 0; mf < 4; mf++)
                #pragma unroll
                for (int nf = 0; nf < 4; nf++) {
                    asm volatile(
                        "mma.sync.aligned.m16n8k16.row.col.f32.f16.f16.f32 "
                        "{%0,%1,%2,%3}, {%4,%5,%6,%7}, {%8,%9}, {%0,%1,%2,%3};\n"
                        : "+f"(acc[mf][nf][0]), "+f"(acc[mf][nf][1]),
                          "+f"(acc[mf][nf][2]), "+f"(acc[mf][nf][3])
                        : "r"(a[mf][0]), "r"(a[mf][1]), "r"(a[mf][2]), "r"(a[mf][3]),
                          "r"(b[nf][0]), "r"(b[nf][1]));
                }
        }

        if (i + 3 < niter) loadStage(i + 3, (i + 3) & (NSTAGE - 1));
        asm volatile("cp.async.commit_group;");   // exactly one group per iter
    }

    // ---- epilogue: bias + relu + scale; fp32 or fp16 stores ----
    const int rowBase = blockIdx.y * BMt + wm * 64 + lr;
    const int colBase = blockIdx.x * BNt + wn * 32 + lc * 2;
    #pragma unroll
    for (int mf = 0; mf < 4; mf++) {
        #pragma unroll
        for (int nf = 0; nf < 4; nf++) {
            int r0 = rowBase + mf * 16;
            int c0 = colBase + nf * 8;
            float b0 = bias ? bias[c0]     : 0.f;
            float b1 = bias ? bias[c0 + 1] : 0.f;
            float v0 = acc[mf][nf][0] + b0;
            float v1 = acc[mf][nf][1] + b1;
            float v2 = acc[mf][nf][2] + b0;
            float v3 = acc[mf][nf][3] + b1;
            if (doRelu) {
                v0 = fmaxf(v0, 0.f); v1 = fmaxf(v1, 0.f);
                v2 = fmaxf(v2, 0.f); v3 = fmaxf(v3, 0.f);
            }
            v0 *= scale; v1 *= scale; v2 *= scale; v3 *= scale;
            if (Ch) {
                *(__half2*)(Ch + (size_t)r0 * ldc + c0) =
                    __floats2half2_rn(v0, v1);
                *(__half2*)(Ch + (size_t)(r0 + 8) * ldc + c0) =
                    __floats2half2_rn(v2, v3);
            } else {
                *(float2*)(C + (size_t)r0 * ldc + c0)       = make_float2(v0, v1);
                *(float2*)(C + (size_t)(r0 + 8) * ldc + c0) = make_float2(v2, v3);
            }
        }
    }
}

// -------- weight transpose: S[R,C] fp32 -> D[C,R] fp16, half2 stores ----------
__global__ void k_transpose_h(const float* __restrict__ S, __half* __restrict__ Dd,
                              int R, int Cc)
{
    __shared__ float t[32][33];
    int c0 = blockIdx.x * 32, r0 = blockIdx.y * 32;
    int x = threadIdx.x, y = threadIdx.y;   // 32 x 8
    #pragma unroll
    for (int k = 0; k < 32; k += 8)
        t[y + k][x] = S[(size_t)(r0 + y + k) * Cc + c0 + x];
    __syncthreads();
    // write phase: 256 threads, each stores 2 half2 (coalesced 4B stores)
    int tid = y * 32 + x;
    int xs  = (tid & 15) * 2;        // 0,2,..,30 (pair along R)
    int ys  = tid >> 4;              // 0..15
    #pragma unroll
    for (int j = 0; j < 2; j++) {
        int row = ys + j * 16;       // output row (c0+row)
        __half2 hv = __floats2half2_rn(t[xs][row], t[xs + 1][row]);
        *(__half2*)(Dd + (size_t)(c0 + row) * R + r0 + xs) = hv;
    }
}

// ---------------- embedding gather -> fp16 --------------------------------------
__global__ void k_embed(const int* __restrict__ tokens, const float* __restrict__ E) {
    int i = blockIdx.x * blockDim.x + threadIdx.x;      // over BT_*D_/4 float4s
    int row = i / (D_ / 4);
    int c4  = i % (D_ / 4);
    int tok = tokens[row];
    float4 v = ((const float4*)(E + (size_t)tok * D_))[c4];
    ((__half2*)g_embh)[i * 2]     = __floats2half2_rn(v.x, v.y);
    ((__half2*)g_embh)[i * 2 + 1] = __floats2half2_rn(v.z, v.w);
}

// ---------------- chunked prefix scan of Yh over t -----------------------------
__global__ void k_chunksum() {
    int g = blockIdx.x * blockDim.x + threadIdx.x;
    int h = g % H_;
    int c = (g / H_) % NCHUNK;
    int b = g / (H_ * NCHUNK);
    const float* base = g_yh + ((size_t)(b * T_ + c * CHLEN)) * H_ + h;
    float s = 0.f;
    #pragma unroll 8
    for (int j = 0; j < CHLEN; j++) s += base[(size_t)j * H_];
    g_csum[(b * NCHUNK + c) * H_ + h] = s;
}

__global__ void k_scan() {
    int g = blockIdx.x * blockDim.x + threadIdx.x;
    int h = g % H_;
    int b = g / H_;
    float run = 0.f;
    #pragma unroll
    for (int c = 0; c < NCHUNK; c++) {
        int idx = (b * NCHUNK + c) * H_ + h;
        float t = g_csum[idx];
        g_csum[idx] = run;
        run += t;
    }
}

__global__ void k_hist(const float* __restrict__ bh) {
    int g = blockIdx.x * blockDim.x + threadIdx.x;
    int h = g % H_;
    int c = (g / H_) % NCHUNK;
    int b = g / (H_ * NCHUNK);
    float excl = g_csum[(b * NCHUNK + c) * H_ + h];
    float bias = bh[h];
    #pragma unroll 4
    for (int j = 0; j < CHLEN; j++) {
        int t = c * CHLEN + j;
        float y = g_yh[((size_t)(b * T_ + t)) * H_ + h];
        float val = (t == 0) ? y : excl / (float)t;
        excl += y;
        float o = fmaxf(val + bias, 0.f);
        g_mergedh[((size_t)(b * T_ + t)) * (2 * H_) + H_ + h] = __float2half_rn(o);
    }
}

// ---------------- LayerNorm over H=1024 per row -> fp16 out --------------------
__global__ __launch_bounds__(256) void k_ln(const float* __restrict__ X,
                                            const float* __restrict__ w,
                                            const float* __restrict__ b)
{
    int row = blockIdx.x;
    int tid = threadIdx.x;
    const float* x = X + (size_t)row * H_;
    float4 v = ((const float4*)x)[tid];
    float s  = v.x + v.y + v.z + v.w;
    float sq = v.x * v.x + v.y * v.y + v.z * v.z + v.w * v.w;

    __shared__ float sh[2][8];
    #pragma unroll
    for (int o = 16; o; o >>= 1) {
        s  += __shfl_xor_sync(0xffffffffu, s, o);
        sq += __shfl_xor_sync(0xffffffffu, sq, o);
    }
    if ((tid & 31) == 0) { sh[0][tid >> 5] = s; sh[1][tid >> 5] = sq; }
    __syncthreads();
    if (tid < 32) {
        s  = (tid < 8) ? sh[0][tid] : 0.f;
        sq = (tid < 8) ? sh[1][tid] : 0.f;
        #pragma unroll
        for (int o = 4; o; o >>= 1) {
            s  += __shfl_xor_sync(0xffffffffu, s, o);
            sq += __shfl_xor_sync(0xffffffffu, sq, o);
        }
        if (tid == 0) { sh[0][0] = s; sh[1][0] = sq; }
    }
    __syncthreads();
    float mu   = sh[0][0] * (1.f / H_);
    float var  = sh[1][0] * (1.f / H_) - mu * mu;
    float rstd = rsqrtf(var + 1e-5f);

    float4 wv = ((const float4*)w)[tid];
    float4 bv = ((const float4*)b)[tid];
    float o0 = (v.x - mu) * rstd * wv.x + bv.x;
    float o1 = (v.y - mu) * rstd * wv.y + bv.y;
    float o2 = (v.z - mu) * rstd * wv.z + bv.z;
    float o3 = (v.w - mu) * rstd * wv.w + bv.w;
    size_t base2 = ((size_t)row * H_) / 2 + tid * 2;
    ((__half2*)g_normedh)[base2]     = __floats2half2_rn(o0, o1);
    ((__half2*)g_normedh)[base2 + 1] = __floats2half2_rn(o2, o3);
}

// ---------------- launch --------------------------------------------------------
extern "C" void kernel_launch(void* const* d_in, const int* in_sizes, int n_in,
                              void* d_out, int out_size)
{
    const int*   tokens = (const int*)  d_in[0];
    const float* E    = (const float*)d_in[1];
    const float* Wc   = (const float*)d_in[2];
    const float* bc   = (const float*)d_in[3];
    const float* Wh   = (const float*)d_in[4];
    const float* bh   = (const float*)d_in[5];
    const float* Wm   = (const float*)d_in[6];
    const float* bm   = (const float*)d_in[7];
    const float* Wo   = (const float*)d_in[8];
    const float* bo   = (const float*)d_in[9];
    const float* ln_w = (const float*)d_in[10];
    const float* ln_b = (const float*)d_in[11];
    float* out = (float*)d_out;

    __half *embh, *mergedh, *normedh, *wchT, *whhT, *wmhT, *wohT;
    float *yh;
    cudaGetSymbolAddress((void**)&embh,    g_embh);
    cudaGetSymbolAddress((void**)&mergedh, g_mergedh);
    cudaGetSymbolAddress((void**)&normedh, g_normedh);
    cudaGetSymbolAddress((void**)&wchT,    g_wchT);
    cudaGetSymbolAddress((void**)&whhT,    g_whhT);
    cudaGetSymbolAddress((void**)&wmhT,    g_wmhT);
    cudaGetSymbolAddress((void**)&wohT,    g_wohT);
    cudaGetSymbolAddress((void**)&yh,      g_yh);

    cudaFuncSetAttribute(tc_gemm, cudaFuncAttributeMaxDynamicSharedMemorySize,
                         TC_SMEM);

    dim3 tb(32, 8);
    // weight transposes -> K-major fp16
    k_transpose_h<<<dim3(H_ / 32,  D_ / 32),     tb>>>(Wc, wchT, D_,     H_);
    k_transpose_h<<<dim3(H_ / 32,  D_ / 32),     tb>>>(Wh, whhT, D_,     H_);
    k_transpose_h<<<dim3(H_ / 32,  2 * H_ / 32), tb>>>(Wm, wmhT, 2 * H_, H_);
    k_transpose_h<<<dim3(V_ / 32,  H_ / 32),     tb>>>(Wo, wohT, H_,     V_);

    // 1) gather embeddings -> fp16
    k_embed<<<(BT_ * D_ / 4) / 256, 256>>>(tokens, E);

    // 2) cur_enc = relu(emb@Wc + bc) -> fp16 into merged left half (ldc=2H)
    tc_gemm<<<dim3(H_ / BNt, BT_ / BMt), 256, TC_SMEM>>>(
        embh, wchT, nullptr, mergedh, D_, 2 * H_, bc, 1, 1.f);

    // 3) Yh = emb@Wh -> fp32
    tc_gemm<<<dim3(H_ / BNt, BT_ / BMt), 256, TC_SMEM>>>(
        embh, whhT, yh, nullptr, D_, H_, nullptr, 0, 1.f);

    // 4-6) hist_enc = relu(cumsum(Yh)/count + bh) -> fp16 merged right half
    k_chunksum<<<(B_ * NCHUNK * H_) / 256, 256>>>();
    k_scan<<<(B_ * H_) / 256, 256>>>();
    k_hist<<<(B_ * NCHUNK * H_) / 256, 256>>>(bh);

    // 7) merged2 = relu(merged@Wm + bm) (K=2048) -> fp32 g_yh (LN input)
    tc_gemm<<<dim3(H_ / BNt, BT_ / BMt), 256, TC_SMEM>>>(
        mergedh, wmhT, yh, nullptr, 2 * H_, H_, bm, 1, 1.f);

    // 8) layernorm -> fp16 normed
    k_ln<<<BT_, 256>>>(yh, ln_w, ln_b);

    // 9) logits = (normed@Wo + bo) * 0.1  (268 GF dominant GEMM)
    tc_gemm<<<dim3(V_ / BNt, BT_ / BMt), 256, TC_SMEM>>>(
        normedh, wohT, out, nullptr, H_, V_, bo, 0, 0.1f);
}